// round 14
// baseline (speedup 1.0000x reference)
#include <cuda_runtime.h>
#include <cuda_bf16.h>
#include <cstdint>
#include <cstddef>

#define B_ 16
#define T_ 512
#define E_ 768
#define H_ 12
#define D_ 64
#define L_ 100
#define MROWS (B_*T_)   // 8192
#define NEGBIG (-1e9f)
typedef __nv_bfloat16 bf16;

// ---------------- scratch (__device__ globals; alloc-free rule) ----------------
__device__ bf16 g_Xhi[MROWS*E_], g_Xlo[MROWS*E_];
__device__ bf16 g_atthi[MROWS*128], g_attlo[MROWS*128];
__device__ float g_ht[MROWS*E_];
__device__ bf16 g_hthi[MROWS*E_], g_htlo[MROWS*E_];
__device__ bf16 g_qhi[MROWS*E_], g_qlo[MROWS*E_];   // [b,h,t,d]
__device__ bf16 g_khi[MROWS*E_], g_klo[MROWS*E_];   // [b,h,t,d]
__device__ bf16 g_vhi[MROWS*E_], g_vlo[MROWS*E_];   // [b,h,d,t]
__device__ bf16 g_ctxhi[MROWS*E_], g_ctxlo[MROWS*E_];
__device__ float g_z[MROWS*E_];
__device__ bf16 g_Wqthi[E_*E_], g_Wqtlo[E_*E_];
__device__ bf16 g_Wkthi[E_*E_], g_Wktlo[E_*E_];
__device__ bf16 g_Wvthi[E_*E_], g_Wvtlo[E_*E_];
__device__ bf16 g_Wothi[E_*E_], g_Wotlo[E_*E_];
__device__ bf16 g_TEhi[128*E_], g_TElo[128*E_];
__device__ bf16 g_TEthi[E_*128], g_TEtlo[E_*128];
__device__ float g_bq2[E_];

// ---------------- helpers ----------------
__device__ __forceinline__ uint32_t smem_u32(const void* p){
    uint32_t a;
    asm("{ .reg .u64 t; cvta.to.shared.u64 t, %1; cvt.u32.u64 %0, t; }":"=r"(a):"l"(p));
    return a;
}
__device__ __forceinline__ void cp16(uint32_t dst, const void* src){
    asm volatile("cp.async.cg.shared.global [%0], [%1], 16;" :: "r"(dst), "l"(src));
}
#define CP_COMMIT() asm volatile("cp.async.commit_group;":::"memory")
#define CP_WAIT1()  asm volatile("cp.async.wait_group 1;":::"memory")
#define CP_WAIT0()  asm volatile("cp.async.wait_group 0;":::"memory")

__device__ __forceinline__ void mma16816(float* c, const uint32_t* a, const uint32_t* b){
    asm volatile(
        "mma.sync.aligned.m16n8k16.row.col.f32.bf16.bf16.f32 "
        "{%0,%1,%2,%3}, {%4,%5,%6,%7}, {%8,%9}, {%0,%1,%2,%3};"
        : "+f"(c[0]), "+f"(c[1]), "+f"(c[2]), "+f"(c[3])
        : "r"(a[0]), "r"(a[1]), "r"(a[2]), "r"(a[3]), "r"(b[0]), "r"(b[1]));
}
__device__ __forceinline__ void ldsm4(uint32_t* r, uint32_t addr){
    asm volatile("ldmatrix.sync.aligned.m8n8.x4.shared.b16 {%0,%1,%2,%3}, [%4];"
        : "=r"(r[0]), "=r"(r[1]), "=r"(r[2]), "=r"(r[3]) : "r"(addr));
}

__device__ __forceinline__ void pack2(float a, float b, uint32_t& hi, uint32_t& lo){
    bf16 ha = __float2bfloat16(a), hb = __float2bfloat16(b);
    bf16 la = __float2bfloat16(a - __bfloat162float(ha));
    bf16 lb = __float2bfloat16(b - __bfloat162float(hb));
    __nv_bfloat162 hp; hp.x = ha; hp.y = hb;
    __nv_bfloat162 lp; lp.x = la; lp.y = lb;
    hi = *(uint32_t*)&hp;
    lo = *(uint32_t*)&lp;
}
__device__ __forceinline__ uint32_t pack2hi(float a, float b){
    __nv_bfloat162 hp;
    hp.x = __float2bfloat16(a);
    hp.y = __float2bfloat16(b);
    return *(uint32_t*)&hp;
}

#define AST 40   // GEMM smem row stride (bf16); 80B rows, LDSM conflict-free
// 128x128 tile, stage = 4 mats x 128*AST bf16 = 40960 bytes
#define GSTG_BYTES 40960u

// ---- GEMM core context (128x128 CTA tile, 8 warps of 64x32) ----
struct GemmCtx {
    uint32_t fs_u, aoff, boff;
    int wm, wn, g, tg;
};
__device__ __forceinline__ GemmCtx gemm_ctx(const bf16* smem){
    GemmCtx c;
    int tid = threadIdx.x;
    int lane = tid & 31, wid = tid >> 5;
    c.wm = wid & 1; c.wn = wid >> 1;
    c.g = lane >> 2; c.tg = lane & 3;
    c.fs_u = smem_u32(smem);
    c.aoff = (uint32_t)(((c.wm << 6) + (lane & 15)) * 80 + ((lane >> 4) << 4));
    c.boff = (uint32_t)(((c.wn << 5) + ((lane >> 4) << 3) + (lane & 7)) * 80
                        + (((lane >> 3) & 1) << 4));
    return c;
}

// issue one k32 stage: A/B 128 rows each, hi+lo
__device__ __forceinline__ void gemm_issue(bf16* smem, int st, int k0,
    const bf16* __restrict__ Ahi, const bf16* __restrict__ Alo, int lda, int m0,
    const bf16* __restrict__ Bhi, const bf16* __restrict__ Blo, int ldb, int n0)
{
    const int tid = threadIdx.x;
    bf16* base = smem + st * 20480;   // 40960 bytes / 2
    const bf16* srcs[4] = {Ahi, Alo, Bhi, Blo};
    const int   lds_[4] = {lda, lda, ldb, ldb};
    const int   r0s_[4] = {m0, m0, n0, n0};
    #pragma unroll
    for (int mat = 0; mat < 4; mat++){
        bf16* dstm = base + mat * 5120;
        #pragma unroll
        for (int it = 0; it < 2; it++){
            int idx = tid + (it << 8);
            int r = idx >> 2, c = idx & 3;
            cp16(smem_u32(dstm + r * AST + c * 8),
                 srcs[mat] + (size_t)(r0s_[mat] + r) * lds_[mat] + k0 + c * 8);
        }
    }
    CP_COMMIT();
}

__device__ __forceinline__ void gemm_stage_mma(const GemmCtx& c, int s, float acc[4][4][4]){
    const uint32_t stg = c.fs_u + (uint32_t)((s & 1) * GSTG_BYTES);
    #pragma unroll
    for (int kh = 0; kh < 2; kh++){
        const uint32_t kb32 = (uint32_t)(kh << 5);
        uint32_t bfh[8], bfl[8];
        ldsm4(bfh,     stg + 20480u + c.boff + kb32);
        ldsm4(bfh + 4, stg + 20480u + c.boff + 1280u + kb32);
        ldsm4(bfl,     stg + 30720u + c.boff + kb32);
        ldsm4(bfl + 4, stg + 30720u + c.boff + 1280u + kb32);
        #pragma unroll
        for (int mt = 0; mt < 4; mt++){
            uint32_t ah[4], al[4];
            ldsm4(ah, stg + c.aoff + (uint32_t)(mt * 1280) + kb32);
            ldsm4(al, stg + 10240u + c.aoff + (uint32_t)(mt * 1280) + kb32);
            #pragma unroll
            for (int nt = 0; nt < 4; nt++){
                mma16816(acc[mt][nt], ah, bfh + nt * 2);
                mma16816(acc[mt][nt], al, bfh + nt * 2);
                mma16816(acc[mt][nt], ah, bfl + nt * 2);
            }
        }
    }
}

// ---------------- split-bf16 HMMA GEMM: C[M,N] = A @ B^T (+epilogue) ----------------
// EPI: 0 = scores (store [M,100], guard n<100)
//      2 = +Xres, store fp32 C and bf16 split Chi/Clo   (h_truth)
//      3 = +bias +Xres +tp, store fp32                  (z)
template<int EPI>
__global__ __launch_bounds__(256, 2)
void mma_gemm(const bf16* __restrict__ Ahi, const bf16* __restrict__ Alo, int lda,
              const bf16* __restrict__ Bhi, const bf16* __restrict__ Blo, int ldb,
              int K,
              const float* __restrict__ bias, const float* __restrict__ Xres,
              const float* __restrict__ tp,
              float* __restrict__ C,
              bf16* __restrict__ Chi, bf16* __restrict__ Clo)
{
    extern __shared__ bf16 smem[];
    const int m0 = blockIdx.y << 7, n0 = blockIdx.x << 7;
    GemmCtx c = gemm_ctx(smem);
    float acc[4][4][4] = {};
    const int nst = K >> 5;

    gemm_issue(smem, 0, 0, Ahi, Alo, lda, m0, Bhi, Blo, ldb, n0);
    if (nst > 1) gemm_issue(smem, 1, 32, Ahi, Alo, lda, m0, Bhi, Blo, ldb, n0);

    for (int s = 0; s < nst; s++){
        if (s + 1 < nst) CP_WAIT1(); else CP_WAIT0();
        __syncthreads();
        gemm_stage_mma(c, s, acc);
        __syncthreads();
        if (s + 2 < nst)
            gemm_issue(smem, s & 1, (s + 2) << 5, Ahi, Alo, lda, m0, Bhi, Blo, ldb, n0);
    }

    // epilogue
    #pragma unroll
    for (int mt = 0; mt < 4; mt++){
        #pragma unroll
        for (int nt = 0; nt < 4; nt++){
            int ca = n0 + (c.wn << 5) + (nt << 3) + c.tg * 2;
            #pragma unroll
            for (int half = 0; half < 2; half++){
                int row = m0 + (c.wm << 6) + (mt << 4) + c.g + (half << 3);
                float v0 = acc[mt][nt][half * 2];
                float v1 = acc[mt][nt][half * 2 + 1];
                if (EPI == 0){
                    float* Crow = C + (size_t)row * L_;
                    if (ca     < L_) Crow[ca]     = v0;
                    if (ca + 1 < L_) Crow[ca + 1] = v1;
                } else {
                    size_t o = (size_t)row * E_ + ca;
                    if (EPI == 3){ v0 += bias[ca]; v1 += bias[ca + 1]; }
                    v0 += Xres[o]; v1 += Xres[o + 1];
                    if (EPI == 3){ v0 += tp[ca]; v1 += tp[ca + 1]; }
                    float2 f2; f2.x = v0; f2.y = v1;
                    *(float2*)(C + o) = f2;
                    if (EPI == 2){
                        uint32_t hp, lp;
                        pack2(v0, v1, hp, lp);
                        *(uint32_t*)(Chi + o) = hp;
                        *(uint32_t*)(Clo + o) = lp;
                    }
                }
            }
        }
    }
}

// ---------------- fused q/k/v projection (zbase + blockIdx.z selects) ----------------
__global__ __launch_bounds__(256, 2)
void qkv_gemm(const float* __restrict__ bk, const float* __restrict__ bv, int zbase)
{
    extern __shared__ bf16 smem[];
    const int m0 = blockIdx.y << 7, n0 = blockIdx.x << 7;
    const int z = blockIdx.z + zbase;
    const bf16 *Ahi, *Alo, *Bh, *Bl;
    const float* bias;
    bf16 *Chi, *Clo;
    float scale;
    if (z == 0){
        Ahi = g_Xhi;  Alo = g_Xlo;  Bh = g_Wqthi; Bl = g_Wqtlo;
        bias = g_bq2; scale = 0.125f; Chi = g_qhi; Clo = g_qlo;
    } else if (z == 1){
        Ahi = g_hthi; Alo = g_htlo; Bh = g_Wkthi; Bl = g_Wktlo;
        bias = bk;    scale = 1.f;   Chi = g_khi; Clo = g_klo;
    } else {
        Ahi = g_hthi; Alo = g_htlo; Bh = g_Wvthi; Bl = g_Wvtlo;
        bias = bv;    scale = 1.f;   Chi = g_vhi; Clo = g_vlo;
    }

    GemmCtx c = gemm_ctx(smem);
    float acc[4][4][4] = {};
    const int nst = E_ >> 5;   // 24

    gemm_issue(smem, 0, 0, Ahi, Alo, E_, m0, Bh, Bl, E_, n0);
    gemm_issue(smem, 1, 32, Ahi, Alo, E_, m0, Bh, Bl, E_, n0);

    for (int s = 0; s < nst; s++){
        if (s + 1 < nst) CP_WAIT1(); else CP_WAIT0();
        __syncthreads();
        gemm_stage_mma(c, s, acc);
        __syncthreads();
        if (s + 2 < nst)
            gemm_issue(smem, s & 1, (s + 2) << 5, Ahi, Alo, E_, m0, Bh, Bl, E_, n0);
    }

    #pragma unroll
    for (int mt = 0; mt < 4; mt++){
        #pragma unroll
        for (int nt = 0; nt < 4; nt++){
            int ca = n0 + (c.wn << 5) + (nt << 3) + c.tg * 2;
            #pragma unroll
            for (int half = 0; half < 2; half++){
                int row = m0 + (c.wm << 6) + (mt << 4) + c.g + (half << 3);
                float v0 = (acc[mt][nt][half * 2]     + bias[ca])     * scale;
                float v1 = (acc[mt][nt][half * 2 + 1] + bias[ca + 1]) * scale;
                int bb = row >> 9, t = row & 511;
                int hh = ca >> 6, d = ca & 63;
                bf16 h0 = __float2bfloat16(v0);
                bf16 h1 = __float2bfloat16(v1);
                bf16 l0 = __float2bfloat16(v0 - __bfloat162float(h0));
                bf16 l1 = __float2bfloat16(v1 - __bfloat162float(h1));
                if (z <= 1){
                    size_t dst = (((size_t)bb * H_ + hh) * T_ + t) * 64 + d;
                    __nv_bfloat162 hp; hp.x = h0; hp.y = h1;
                    __nv_bfloat162 lp; lp.x = l0; lp.y = l1;
                    *(__nv_bfloat162*)(Chi + dst) = hp;
                    *(__nv_bfloat162*)(Clo + dst) = lp;
                } else {
                    size_t dst = (((size_t)bb * H_ + hh) * 64 + d) * T_ + t;
                    Chi[dst] = h0; Chi[dst + T_] = h1;
                    Clo[dst] = l0; Clo[dst + T_] = l1;
                }
            }
        }
    }
}

// ---------------- prep kernels ----------------
__global__ __launch_bounds__(256)
void split_kernel(const float* __restrict__ x, bf16* __restrict__ hi,
                  bf16* __restrict__ lo, int n)
{
    int i = blockIdx.x * 256 + threadIdx.x;
    if (i >= n) return;
    float v = x[i];
    bf16 h = __float2bfloat16(v);
    hi[i] = h;
    lo[i] = __float2bfloat16(v - __bfloat162float(h));
}

// all 4 weight transposes in one launch (grid.z selects)
__global__ __launch_bounds__(256)
void transW_all(const float* __restrict__ Wq, const float* __restrict__ Wk,
                const float* __restrict__ Wv, const float* __restrict__ Wo)
{
    __shared__ float t[32][33];
    const int z = blockIdx.z;
    const float* W = (z == 0) ? Wq : (z == 1) ? Wk : (z == 2) ? Wv : Wo;
    bf16* Thi = (z == 0) ? g_Wqthi : (z == 1) ? g_Wkthi : (z == 2) ? g_Wvthi : g_Wothi;
    bf16* Tlo = (z == 0) ? g_Wqtlo : (z == 1) ? g_Wktlo : (z == 2) ? g_Wvtlo : g_Wotlo;
    int k0 = blockIdx.x * 32, n0 = blockIdx.y * 32;
    int tx = threadIdx.x & 31, ty = threadIdx.x >> 5;   // 32x8
    #pragma unroll
    for (int i = 0; i < 4; i++)
        t[ty + 8 * i][tx] = W[(size_t)(k0 + ty + 8 * i) * E_ + n0 + tx];
    __syncthreads();
    #pragma unroll
    for (int i = 0; i < 4; i++){
        float v = t[tx][ty + 8 * i];
        size_t o = (size_t)(n0 + ty + 8 * i) * E_ + k0 + tx;
        bf16 h = __float2bfloat16(v);
        Thi[o] = h;
        Tlo[o] = __float2bfloat16(v - __bfloat162float(h));
    }
}

__global__ __launch_bounds__(256)
void tePad_kernel(const float* __restrict__ TE, bf16* __restrict__ hi,
                  bf16* __restrict__ lo)
{
    int i = blockIdx.x * 256 + threadIdx.x;    // over 128*768
    if (i >= 128 * E_) return;
    int l = i / E_, e = i % E_;
    float v = (l < L_) ? TE[(size_t)l * E_ + e] : 0.f;
    bf16 h = __float2bfloat16(v);
    hi[i] = h;
    lo[i] = __float2bfloat16(v - __bfloat162float(h));
}

__global__ __launch_bounds__(256)
void teT_kernel(const float* __restrict__ TE, bf16* __restrict__ hi,
                bf16* __restrict__ lo)
{
    int i = blockIdx.x * 256 + threadIdx.x;    // over 768*128
    if (i >= E_ * 128) return;
    int e = i >> 7, l = i & 127;
    float v = (l < L_) ? TE[(size_t)l * E_ + e] : 0.f;
    bf16 h = __float2bfloat16(v);
    hi[i] = h;
    lo[i] = __float2bfloat16(v - __bfloat162float(h));
}

__global__ __launch_bounds__(256)
void biasq_kernel(const float* __restrict__ tp, const float* __restrict__ Wq,
                  const float* __restrict__ bq, float* __restrict__ out)
{
    int n = blockIdx.x * 256 + threadIdx.x;
    if (n >= E_) return;
    float acc = bq[n];
    for (int k2 = 0; k2 < E_; k2++) acc += tp[k2] * Wq[(size_t)k2 * E_ + n];
    out[n] = acc;
}

// ---------------- softmax over L=100, writes bf16 split padded to 128 ----------------
__global__ __launch_bounds__(256)
void softmax100_kernel(const float* __restrict__ scores,
                       bf16* __restrict__ atthi, bf16* __restrict__ attlo)
{
    int warp = (blockIdx.x * blockDim.x + threadIdx.x) >> 5;
    int lane = threadIdx.x & 31;
    if (warp >= MROWS) return;
    const float* s = scores + (size_t)warp * L_;
    float v[4];
    float mx = -INFINITY;
    #pragma unroll
    for (int i = 0; i < 4; i++){
        int l = lane + i * 32;
        v[i] = (l < L_) ? s[l] : -INFINITY;
        mx = fmaxf(mx, v[i]);
    }
    #pragma unroll
    for (int w = 16; w; w >>= 1) mx = fmaxf(mx, __shfl_xor_sync(0xffffffffu, mx, w));
    float sum = 0.f;
    #pragma unroll
    for (int i = 0; i < 4; i++){
        int l = lane + i * 32;
        v[i] = (l < L_) ? expf(v[i] - mx) : 0.f;
        sum += v[i];
    }
    #pragma unroll
    for (int w = 16; w; w >>= 1) sum += __shfl_xor_sync(0xffffffffu, sum, w);
    float inv = 1.f / sum;
    #pragma unroll
    for (int i = 0; i < 4; i++){
        int l = lane + i * 32;
        float p = (l < L_) ? v[i] * inv : 0.f;
        bf16 h = __float2bfloat16(p);
        atthi[(size_t)warp * 128 + l] = h;
        attlo[(size_t)warp * 128 + l] = __float2bfloat16(p - __bfloat162float(h));
    }
}

// ---------------- tensor-core flash attention (split-bf16, LDSM) ----------------
#define FST 72   // flash smem row stride (bf16); 144B rows, LDSM conflict-free
__global__ __launch_bounds__(256, 2)
void flash_mma(const bf16* __restrict__ qh_g, const bf16* __restrict__ ql_g,
               const bf16* __restrict__ kh_g, const bf16* __restrict__ kl_g,
               const bf16* __restrict__ vh_g, const bf16* __restrict__ vl_g,
               const float* __restrict__ amask,
               bf16* __restrict__ ctxhi, bf16* __restrict__ ctxlo)
{
    extern __shared__ bf16 fs[];
    const int b = blockIdx.z, h = blockIdx.y, q0 = blockIdx.x << 7;
    const int tid = threadIdx.x, lane = tid & 31, w = tid >> 5;
    const int g = lane >> 2, tg = lane & 3;
    const int bh = b * H_ + h;

    bf16* sQh = fs;
    bf16* sQl = fs + 9216;           // 128*72
    float* sM = (float*)(fs + 55296);
    const uint32_t fs_u = smem_u32(fs);

    // mask bias into smem
    sM[tid]       = (1.f - amask[(size_t)b * T_ + tid])       * NEGBIG;
    sM[tid + 256] = (1.f - amask[(size_t)b * T_ + tid + 256]) * NEGBIG;

    // LDSM per-lane offsets (bytes)
    const uint32_t qoff = (uint32_t)(((w << 4) + (lane & 15)) * 144 + ((lane >> 4) << 4));
    const uint32_t koff = (uint32_t)((((lane >> 4) << 3) + (lane & 7)) * 144
                                     + (((lane >> 3) & 1) << 4));

    // issue Q (hi+lo): 128 rows x 8 chunks x 2 mats
    #pragma unroll
    for (int it = 0; it < 8; it++){
        int mat = it >> 2;
        int idx = tid + ((it & 3) << 8);
        int r = idx >> 3, c = idx & 7;
        const bf16* src = (mat ? ql_g : qh_g) + ((size_t)bh * T_ + q0 + r) * 64 + c * 8;
        cp16(smem_u32((mat ? sQl : sQh) + r * FST + c * 8), src);
    }
    CP_COMMIT();

    auto issueT = [&](int buf, int kt){
        #pragma unroll
        for (int it = 0; it < 8; it++){
            int mat = it >> 1;
            int idx = tid + ((it & 1) << 8);
            int r = idx >> 3, c = idx & 7;
            const bf16* src;
            if (mat == 0)      src = kh_g + ((size_t)bh * T_ + kt * 64 + r) * 64 + c * 8;
            else if (mat == 1) src = kl_g + ((size_t)bh * T_ + kt * 64 + r) * 64 + c * 8;
            else if (mat == 2) src = vh_g + ((size_t)bh * 64 + r) * T_ + kt * 64 + c * 8;
            else               src = vl_g + ((size_t)bh * 64 + r) * T_ + kt * 64 + c * 8;
            cp16(smem_u32(fs + 18432 + buf * 18432 + mat * 4608 + r * FST + c * 8), src);
        }
        CP_COMMIT();
    };
    issueT(0, 0);
    issueT(1, 1);
    CP_WAIT1();            // Q + tile0 done
    __syncthreads();

    // Q frags (register-resident, reused over all k-tiles)
    uint32_t qh[4][4], ql[4][4];
    #pragma unroll
    for (int kb = 0; kb < 4; kb++){
        ldsm4(qh[kb], fs_u + qoff + (uint32_t)(kb << 5));
        ldsm4(ql[kb], fs_u + 18432u + qoff + (uint32_t)(kb << 5));
    }

    const int qg0 = q0 + (w << 4) + g, qg1 = qg0 + 8;
    float o[8][4] = {};
    float mp0 = -INFINITY, mp1 = -INFINITY, l0 = 0.f, l1 = 0.f;

    for (int kt = 0; kt < 8; kt++){
        if (kt){
            if (kt < 7) CP_WAIT1(); else CP_WAIT0();
            __syncthreads();
        }
        const uint32_t Kh_u = fs_u + 36864u + (uint32_t)((kt & 1) * 36864);
        const uint32_t Kl_u = Kh_u + 9216u;
        const uint32_t Vh_u = Kh_u + 18432u;
        const uint32_t Vl_u = Kh_u + 27648u;

        // S = Q @ K^T  (128x64 per CTA; 16x64 per warp)
        float s[8][4] = {};
        #pragma unroll
        for (int np = 0; np < 4; np++){
            #pragma unroll
            for (int kb = 0; kb < 4; kb++){
                uint32_t k4h[4], k4l[4];
                uint32_t off = koff + (uint32_t)(np * 2304) + (uint32_t)(kb << 5);
                ldsm4(k4h, Kh_u + off);
                ldsm4(k4l, Kl_u + off);
                mma16816(s[2*np],     qh[kb], k4h);
                mma16816(s[2*np],     ql[kb], k4h);
                mma16816(s[2*np],     qh[kb], k4l);
                mma16816(s[2*np+1],   qh[kb], k4h + 2);
                mma16816(s[2*np+1],   ql[kb], k4h + 2);
                mma16816(s[2*np+1],   qh[kb], k4l + 2);
            }
        }

        // mask + online softmax
        float rm0 = -INFINITY, rm1 = -INFINITY;
        #pragma unroll
        for (int nf = 0; nf < 8; nf++){
            int cg = (kt << 6) + (nf << 3) + (tg << 1);
            float ma = sM[cg], mb = sM[cg + 1];
            s[nf][0] += ma + ((cg     == qg0) ? NEGBIG : 0.f);
            s[nf][1] += mb + ((cg + 1 == qg0) ? NEGBIG : 0.f);
            s[nf][2] += ma + ((cg     == qg1) ? NEGBIG : 0.f);
            s[nf][3] += mb + ((cg + 1 == qg1) ? NEGBIG : 0.f);
            rm0 = fmaxf(rm0, fmaxf(s[nf][0], s[nf][1]));
            rm1 = fmaxf(rm1, fmaxf(s[nf][2], s[nf][3]));
        }
        rm0 = fmaxf(rm0, __shfl_xor_sync(0xffffffffu, rm0, 1));
        rm0 = fmaxf(rm0, __shfl_xor_sync(0xffffffffu, rm0, 2));
        rm1 = fmaxf(rm1, __shfl_xor_sync(0xffffffffu, rm1, 1));
        rm1 = fmaxf(rm1, __shfl_xor_sync(0xffffffffu, rm1, 2));

        float mn0 = fmaxf(mp0, rm0), mn1 = fmaxf(mp1, rm1);
        float cf0 = __expf(mp0 - mn0), cf1 = __expf(mp1 - mn1);
        float rs0 = 0.f, rs1 = 0.f;
        #pragma unroll
        for (int nf = 0; nf < 8; nf++){
            s[nf][0] = __expf(s[nf][0] - mn0);
            s[nf][1] = __expf(s[nf][1] - mn0);
            s[nf][2] = __expf(s[nf][2] - mn1);
            s[nf][3] = __expf(s[nf][3] - mn1);
            rs0 += s[nf][0] + s[nf][1];
            rs1 += s[nf][2] + s[nf][3];
        }
        rs0 += __shfl_xor_sync(0xffffffffu, rs0, 1);
        rs0 += __shfl_xor_sync(0xffffffffu, rs0, 2);
        rs1 += __shfl_xor_sync(0xffffffffu, rs1, 1);
        rs1 += __shfl_xor_sync(0xffffffffu, rs1, 2);

        l0 = l0 * cf0 + rs0;
        l1 = l1 * cf1 + rs1;
        mp0 = mn0; mp1 = mn1;
        #pragma unroll
        for (int df = 0; df < 8; df++){
            o[df][0] *= cf0; o[df][1] *= cf0;
            o[df][2] *= cf1; o[df][3] *= cf1;
        }

        // O += P @ V   (P-hi only; dropped P-lo x V-hi term, ~1e-4 final rel err)
        #pragma unroll
        for (int kb = 0; kb < 4; kb++){
            uint32_t ph[4];
            ph[0] = pack2hi(s[2*kb][0],   s[2*kb][1]);
            ph[1] = pack2hi(s[2*kb][2],   s[2*kb][3]);
            ph[2] = pack2hi(s[2*kb+1][0], s[2*kb+1][1]);
            ph[3] = pack2hi(s[2*kb+1][2], s[2*kb+1][3]);
            #pragma unroll
            for (int dp = 0; dp < 4; dp++){
                uint32_t v4h[4], v4l[4];
                uint32_t off = koff + (uint32_t)(dp * 2304) + (uint32_t)(kb << 5);
                ldsm4(v4h, Vh_u + off);
                ldsm4(v4l, Vl_u + off);
                mma16816(o[2*dp],   ph, v4h);
                mma16816(o[2*dp],   ph, v4l);
                mma16816(o[2*dp+1], ph, v4h + 2);
                mma16816(o[2*dp+1], ph, v4l + 2);
            }
        }

        __syncthreads();
        if (kt + 2 < 8) issueT(kt & 1, kt + 2);
    }

    // write ctx (bf16 split) as [b*t, e] rows for the O-projection GEMM
    float i0 = 1.f / l0, i1 = 1.f / l1;
    size_t row0 = (size_t)b * T_ + qg0;
    size_t row1 = (size_t)b * T_ + qg1;
    #pragma unroll
    for (int df = 0; df < 8; df++){
        int d = h * 64 + (df << 3) + (tg << 1);
        uint32_t hp, lp;
        pack2(o[df][0] * i0, o[df][1] * i0, hp, lp);
        *(uint32_t*)(ctxhi + row0 * E_ + d) = hp;
        *(uint32_t*)(ctxlo + row0 * E_ + d) = lp;
        pack2(o[df][2] * i1, o[df][3] * i1, hp, lp);
        *(uint32_t*)(ctxhi + row1 * E_ + d) = hp;
        *(uint32_t*)(ctxlo + row1 * E_ + d) = lp;
    }
}

// ---------------- LayerNorm + final residual ----------------
__global__ __launch_bounds__(256)
void ln_kernel(const float* __restrict__ z, const float* __restrict__ g,
               const float* __restrict__ bb, const float* __restrict__ ht,
               float* __restrict__ out)
{
    const int m = blockIdx.x;
    const int t = threadIdx.x;
    __shared__ float buf[E_];
    __shared__ float red[8];
    const int lane = t & 31, wrp = t >> 5;

    float s = 0.f;
    for (int e = t; e < E_; e += 256){
        float x = z[(size_t)m * E_ + e];
        buf[e] = x;
        s += x;
    }
    #pragma unroll
    for (int w = 16; w; w >>= 1) s += __shfl_xor_sync(0xffffffffu, s, w);
    if (lane == 0) red[wrp] = s;
    __syncthreads();
    float mu = 0.f;
    #pragma unroll
    for (int i = 0; i < 8; i++) mu += red[i];
    mu *= (1.f / E_);
    __syncthreads();

    float vs = 0.f;
    for (int e = t; e < E_; e += 256){
        float d = buf[e] - mu;
        vs += d * d;
    }
    #pragma unroll
    for (int w = 16; w; w >>= 1) vs += __shfl_xor_sync(0xffffffffu, vs, w);
    if (lane == 0) red[wrp] = vs;
    __syncthreads();
    float var = 0.f;
    #pragma unroll
    for (int i = 0; i < 8; i++) var += red[i];
    var *= (1.f / E_);
    float rs = rsqrtf(var + 1e-12f);

    for (int e = t; e < E_; e += 256){
        out[(size_t)m * E_ + e] =
            (buf[e] - mu) * rs * g[e] + bb[e] + ht[(size_t)m * E_ + e];
    }
}

// ---------------- launch ----------------
extern "C" void kernel_launch(void* const* d_in, const int* in_sizes, int n_in,
                              void* d_out, int out_size)
{
    const float* X    = (const float*)d_in[0];
    const float* amsk = (const float*)d_in[1];
    const float* TE   = (const float*)d_in[2];
    const float* tp   = (const float*)d_in[3];
    const float* Wq   = (const float*)d_in[4];
    const float* bq   = (const float*)d_in[5];
    const float* Wk   = (const float*)d_in[6];
    const float* bk   = (const float*)d_in[7];
    const float* Wv   = (const float*)d_in[8];
    const float* bv   = (const float*)d_in[9];
    const float* Wo   = (const float*)d_in[10];
    const float* bo   = (const float*)d_in[11];
    const float* lng  = (const float*)d_in[12];
    const float* lnb  = (const float*)d_in[13];

    float* out    = (float*)d_out;
    float* scores = out + (size_t)MROWS * E_;

    // side stream + fork/join events (host resources; created once, identical
    // work enqueued on every call)
    static cudaStream_t s1 = nullptr;
    static cudaEvent_t  e0 = nullptr, e1 = nullptr;
    if (s1 == nullptr){
        cudaStreamCreateWithFlags(&s1, cudaStreamNonBlocking);
        cudaEventCreateWithFlags(&e0, cudaEventDisableTiming);
        cudaEventCreateWithFlags(&e1, cudaEventDisableTiming);
    }

    bf16 *pXhi, *pXlo, *patthi, *pattlo, *phthi, *phtlo, *pctxhi, *pctxlo;
    bf16 *pqhi, *pqlo, *pkhi, *pklo, *pvhi, *pvlo;
    bf16 *pWo1, *pWo2;
    bf16 *pTE1, *pTE2, *pTEt1, *pTEt2;
    float *pht, *pz, *pbq2;
    cudaGetSymbolAddress((void**)&pXhi,   g_Xhi);
    cudaGetSymbolAddress((void**)&pXlo,   g_Xlo);
    cudaGetSymbolAddress((void**)&patthi, g_atthi);
    cudaGetSymbolAddress((void**)&pattlo, g_attlo);
    cudaGetSymbolAddress((void**)&pht,    g_ht);
    cudaGetSymbolAddress((void**)&phthi,  g_hthi);
    cudaGetSymbolAddress((void**)&phtlo,  g_htlo);
    cudaGetSymbolAddress((void**)&pqhi,   g_qhi);
    cudaGetSymbolAddress((void**)&pqlo,   g_qlo);
    cudaGetSymbolAddress((void**)&pkhi,   g_khi);
    cudaGetSymbolAddress((void**)&pklo,   g_klo);
    cudaGetSymbolAddress((void**)&pvhi,   g_vhi);
    cudaGetSymbolAddress((void**)&pvlo,   g_vlo);
    cudaGetSymbolAddress((void**)&pctxhi, g_ctxhi);
    cudaGetSymbolAddress((void**)&pctxlo, g_ctxlo);
    cudaGetSymbolAddress((void**)&pz,     g_z);
    cudaGetSymbolAddress((void**)&pWo1,   g_Wothi);
    cudaGetSymbolAddress((void**)&pWo2,   g_Wotlo);
    cudaGetSymbolAddress((void**)&pTE1,   g_TEhi);
    cudaGetSymbolAddress((void**)&pTE2,   g_TElo);
    cudaGetSymbolAddress((void**)&pTEt1,  g_TEthi);
    cudaGetSymbolAddress((void**)&pTEt2,  g_TEtlo);
    cudaGetSymbolAddress((void**)&pbq2,   g_bq2);

    const int gsm = 2 * (int)GSTG_BYTES;   // 81920
    cudaFuncSetAttribute(mma_gemm<0>, cudaFuncAttributeMaxDynamicSharedMemorySize, gsm);
    cudaFuncSetAttribute(mma_gemm<2>, cudaFuncAttributeMaxDynamicSharedMemorySize, gsm);
    cudaFuncSetAttribute(mma_gemm<3>, cudaFuncAttributeMaxDynamicSharedMemorySize, gsm);
    cudaFuncSetAttribute(qkv_gemm,    cudaFuncAttributeMaxDynamicSharedMemorySize, gsm);
    const int fsm_bytes = 55296 * (int)sizeof(bf16) + 512 * (int)sizeof(float); // 112640
    cudaFuncSetAttribute(flash_mma, cudaFuncAttributeMaxDynamicSharedMemorySize,
                         fsm_bytes);

    dim3 blk(256);

    // ---- prep on main stream ----
    split_kernel<<<(MROWS * E_ + 255) / 256, blk>>>(X, pXhi, pXlo, MROWS * E_);
    transW_all<<<dim3(24, 24, 4), blk>>>(Wq, Wk, Wv, Wo);
    tePad_kernel<<<(128 * E_ + 255) / 256, blk>>>(TE, pTE1, pTE2);
    biasq_kernel<<<3, blk>>>(tp, Wq, bq, pbq2);

    // ---- fork: q projection on side stream (needs split/transW/biasq only) ----
    cudaEventRecord(e0, 0);
    cudaStreamWaitEvent(s1, e0, 0);
    qkv_gemm<<<dim3(6, 64, 1), blk, gsm, s1>>>(bk, bv, 0);   // q

    // ---- main chain: scores -> softmax -> ht -> k,v ----
    mma_gemm<0><<<dim3(1, 64), blk, gsm>>>(pXhi, pXlo, E_, pTE1, pTE2, E_, E_,
                                           nullptr, nullptr, nullptr,
                                           scores, nullptr, nullptr);
    softmax100_kernel<<<MROWS / 8, blk>>>(scores, patthi, pattlo);
    teT_kernel<<<(E_ * 128 + 255) / 256, blk>>>(TE, pTEt1, pTEt2);
    mma_gemm<2><<<dim3(6, 64), blk, gsm>>>(patthi, pattlo, 128, pTEt1, pTEt2, 128, 128,
                                           nullptr, X, nullptr,
                                           pht, phthi, phtlo);
    qkv_gemm<<<dim3(6, 64, 2), blk, gsm>>>(bk, bv, 1);       // k, v

    // ---- join: flash needs q (s1) and k,v (main) ----
    cudaEventRecord(e1, s1);
    cudaStreamWaitEvent(0, e1, 0);
    flash_mma<<<dim3(4, H_, B_), blk, fsm_bytes>>>(pqhi, pqlo, pkhi, pklo,
                                                   pvhi, pvlo, amsk,
                                                   pctxhi, pctxlo);
    // ---- z = ctx @ Wo + bo + X + tp ----
    mma_gemm<3><<<dim3(6, 64), blk, gsm>>>(pctxhi, pctxlo, E_, pWo1, pWo2, E_, E_,
                                           bo, X, tp,
                                           pz, nullptr, nullptr);
    // ---- out = LN(z) + h_truth ----
    ln_kernel<<<MROWS, blk>>>(pz, lng, lnb, pht, out);
}

// round 15
// speedup vs baseline: 1.0984x; 1.0984x over previous
#include <cuda_runtime.h>
#include <cuda_bf16.h>
#include <cstdint>
#include <cstddef>

#define B_ 16
#define T_ 512
#define E_ 768
#define H_ 12
#define D_ 64
#define L_ 100
#define MROWS (B_*T_)   // 8192
#define NEGBIG (-1e9f)
typedef __nv_bfloat16 bf16;

// ---------------- scratch (__device__ globals; alloc-free rule) ----------------
__device__ bf16 g_Xhi[MROWS*E_], g_Xlo[MROWS*E_];
__device__ bf16 g_atthi[MROWS*128], g_attlo[MROWS*128];
__device__ float g_ht[MROWS*E_];
__device__ bf16 g_hthi[MROWS*E_], g_htlo[MROWS*E_];
__device__ bf16 g_qhi[MROWS*E_], g_qlo[MROWS*E_];   // [b,h,t,d]
__device__ bf16 g_khi[MROWS*E_], g_klo[MROWS*E_];   // [b,h,t,d]
__device__ bf16 g_vhi[MROWS*E_], g_vlo[MROWS*E_];   // [b,h,d,t]
__device__ bf16 g_ctxhi[MROWS*E_], g_ctxlo[MROWS*E_];
__device__ float g_z[MROWS*E_];
__device__ bf16 g_Wqthi[E_*E_], g_Wqtlo[E_*E_];
__device__ bf16 g_Wkthi[E_*E_], g_Wktlo[E_*E_];
__device__ bf16 g_Wvthi[E_*E_], g_Wvtlo[E_*E_];
__device__ bf16 g_Wothi[E_*E_], g_Wotlo[E_*E_];
__device__ bf16 g_TEhi[128*E_], g_TElo[128*E_];
__device__ bf16 g_TEthi[E_*128], g_TEtlo[E_*128];
__device__ float g_bq2[E_];
__device__ float g_bqpart[16*E_];

// ---------------- helpers ----------------
__device__ __forceinline__ uint32_t smem_u32(const void* p){
    uint32_t a;
    asm("{ .reg .u64 t; cvta.to.shared.u64 t, %1; cvt.u32.u64 %0, t; }":"=r"(a):"l"(p));
    return a;
}
__device__ __forceinline__ void cp16(uint32_t dst, const void* src){
    asm volatile("cp.async.cg.shared.global [%0], [%1], 16;" :: "r"(dst), "l"(src));
}
#define CP_COMMIT() asm volatile("cp.async.commit_group;":::"memory")
#define CP_WAIT1()  asm volatile("cp.async.wait_group 1;":::"memory")
#define CP_WAIT0()  asm volatile("cp.async.wait_group 0;":::"memory")

__device__ __forceinline__ void mma16816(float* c, const uint32_t* a, const uint32_t* b){
    asm volatile(
        "mma.sync.aligned.m16n8k16.row.col.f32.bf16.bf16.f32 "
        "{%0,%1,%2,%3}, {%4,%5,%6,%7}, {%8,%9}, {%0,%1,%2,%3};"
        : "+f"(c[0]), "+f"(c[1]), "+f"(c[2]), "+f"(c[3])
        : "r"(a[0]), "r"(a[1]), "r"(a[2]), "r"(a[3]), "r"(b[0]), "r"(b[1]));
}
__device__ __forceinline__ void ldsm4(uint32_t* r, uint32_t addr){
    asm volatile("ldmatrix.sync.aligned.m8n8.x4.shared.b16 {%0,%1,%2,%3}, [%4];"
        : "=r"(r[0]), "=r"(r[1]), "=r"(r[2]), "=r"(r[3]) : "r"(addr));
}

__device__ __forceinline__ void pack2(float a, float b, uint32_t& hi, uint32_t& lo){
    bf16 ha = __float2bfloat16(a), hb = __float2bfloat16(b);
    bf16 la = __float2bfloat16(a - __bfloat162float(ha));
    bf16 lb = __float2bfloat16(b - __bfloat162float(hb));
    __nv_bfloat162 hp; hp.x = ha; hp.y = hb;
    __nv_bfloat162 lp; lp.x = la; lp.y = lb;
    hi = *(uint32_t*)&hp;
    lo = *(uint32_t*)&lp;
}
__device__ __forceinline__ uint32_t pack2hi(float a, float b){
    __nv_bfloat162 hp;
    hp.x = __float2bfloat16(a);
    hp.y = __float2bfloat16(b);
    return *(uint32_t*)&hp;
}

#define AST 40   // GEMM smem row stride (bf16); 80B rows, LDSM conflict-free
// 128x128 tile, stage = 4 mats x 128*AST bf16 = 40960 bytes
#define GSTG_BYTES 40960u

// ---- GEMM core context (128x128 CTA tile, 8 warps of 64x32) ----
struct GemmCtx {
    uint32_t fs_u, aoff, boff;
    int wm, wn, g, tg;
};
__device__ __forceinline__ GemmCtx gemm_ctx(const bf16* smem){
    GemmCtx c;
    int tid = threadIdx.x;
    int lane = tid & 31, wid = tid >> 5;
    c.wm = wid & 1; c.wn = wid >> 1;
    c.g = lane >> 2; c.tg = lane & 3;
    c.fs_u = smem_u32(smem);
    c.aoff = (uint32_t)(((c.wm << 6) + (lane & 15)) * 80 + ((lane >> 4) << 4));
    c.boff = (uint32_t)(((c.wn << 5) + ((lane >> 4) << 3) + (lane & 7)) * 80
                        + (((lane >> 3) & 1) << 4));
    return c;
}

// issue one k32 stage: A/B 128 rows each, hi+lo
__device__ __forceinline__ void gemm_issue(bf16* smem, int st, int k0,
    const bf16* __restrict__ Ahi, const bf16* __restrict__ Alo, int lda, int m0,
    const bf16* __restrict__ Bhi, const bf16* __restrict__ Blo, int ldb, int n0)
{
    const int tid = threadIdx.x;
    bf16* base = smem + st * 20480;   // 40960 bytes / 2
    const bf16* srcs[4] = {Ahi, Alo, Bhi, Blo};
    const int   lds_[4] = {lda, lda, ldb, ldb};
    const int   r0s_[4] = {m0, m0, n0, n0};
    #pragma unroll
    for (int mat = 0; mat < 4; mat++){
        bf16* dstm = base + mat * 5120;
        #pragma unroll
        for (int it = 0; it < 2; it++){
            int idx = tid + (it << 8);
            int r = idx >> 2, c = idx & 3;
            cp16(smem_u32(dstm + r * AST + c * 8),
                 srcs[mat] + (size_t)(r0s_[mat] + r) * lds_[mat] + k0 + c * 8);
        }
    }
    CP_COMMIT();
}

__device__ __forceinline__ void gemm_stage_mma(const GemmCtx& c, int s, float acc[4][4][4]){
    const uint32_t stg = c.fs_u + (uint32_t)((s & 1) * GSTG_BYTES);
    #pragma unroll
    for (int kh = 0; kh < 2; kh++){
        const uint32_t kb32 = (uint32_t)(kh << 5);
        uint32_t bfh[8], bfl[8];
        ldsm4(bfh,     stg + 20480u + c.boff + kb32);
        ldsm4(bfh + 4, stg + 20480u + c.boff + 1280u + kb32);
        ldsm4(bfl,     stg + 30720u + c.boff + kb32);
        ldsm4(bfl + 4, stg + 30720u + c.boff + 1280u + kb32);
        #pragma unroll
        for (int mt = 0; mt < 4; mt++){
            uint32_t ah[4], al[4];
            ldsm4(ah, stg + c.aoff + (uint32_t)(mt * 1280) + kb32);
            ldsm4(al, stg + 10240u + c.aoff + (uint32_t)(mt * 1280) + kb32);
            #pragma unroll
            for (int nt = 0; nt < 4; nt++){
                mma16816(acc[mt][nt], ah, bfh + nt * 2);
                mma16816(acc[mt][nt], al, bfh + nt * 2);
                mma16816(acc[mt][nt], ah, bfl + nt * 2);
            }
        }
    }
}

// ---------------- split-bf16 HMMA GEMM: C[M,N] = A @ B^T (+epilogue) ----------------
// EPI: 0 = scores (store [M,100], guard n<100)
//      2 = +Xres, store fp32 C and bf16 split Chi/Clo   (h_truth)
//      3 = +bias +Xres +tp, store fp32                  (z)
template<int EPI>
__global__ __launch_bounds__(256, 2)
void mma_gemm(const bf16* __restrict__ Ahi, const bf16* __restrict__ Alo, int lda,
              const bf16* __restrict__ Bhi, const bf16* __restrict__ Blo, int ldb,
              int K,
              const float* __restrict__ bias, const float* __restrict__ Xres,
              const float* __restrict__ tp,
              float* __restrict__ C,
              bf16* __restrict__ Chi, bf16* __restrict__ Clo)
{
    extern __shared__ bf16 smem[];
    const int m0 = blockIdx.y << 7, n0 = blockIdx.x << 7;
    GemmCtx c = gemm_ctx(smem);
    float acc[4][4][4] = {};
    const int nst = K >> 5;

    gemm_issue(smem, 0, 0, Ahi, Alo, lda, m0, Bhi, Blo, ldb, n0);
    if (nst > 1) gemm_issue(smem, 1, 32, Ahi, Alo, lda, m0, Bhi, Blo, ldb, n0);

    for (int s = 0; s < nst; s++){
        if (s + 1 < nst) CP_WAIT1(); else CP_WAIT0();
        __syncthreads();
        gemm_stage_mma(c, s, acc);
        __syncthreads();
        if (s + 2 < nst)
            gemm_issue(smem, s & 1, (s + 2) << 5, Ahi, Alo, lda, m0, Bhi, Blo, ldb, n0);
    }

    // epilogue
    #pragma unroll
    for (int mt = 0; mt < 4; mt++){
        #pragma unroll
        for (int nt = 0; nt < 4; nt++){
            int ca = n0 + (c.wn << 5) + (nt << 3) + c.tg * 2;
            #pragma unroll
            for (int half = 0; half < 2; half++){
                int row = m0 + (c.wm << 6) + (mt << 4) + c.g + (half << 3);
                float v0 = acc[mt][nt][half * 2];
                float v1 = acc[mt][nt][half * 2 + 1];
                if (EPI == 0){
                    float* Crow = C + (size_t)row * L_;
                    if (ca     < L_) Crow[ca]     = v0;
                    if (ca + 1 < L_) Crow[ca + 1] = v1;
                } else {
                    size_t o = (size_t)row * E_ + ca;
                    if (EPI == 3){ v0 += bias[ca]; v1 += bias[ca + 1]; }
                    v0 += Xres[o]; v1 += Xres[o + 1];
                    if (EPI == 3){ v0 += tp[ca]; v1 += tp[ca + 1]; }
                    float2 f2; f2.x = v0; f2.y = v1;
                    *(float2*)(C + o) = f2;
                    if (EPI == 2){
                        uint32_t hp, lp;
                        pack2(v0, v1, hp, lp);
                        *(uint32_t*)(Chi + o) = hp;
                        *(uint32_t*)(Clo + o) = lp;
                    }
                }
            }
        }
    }
}

// ---------------- fused q/k/v projection (grid.z selects operand set) ----------------
__global__ __launch_bounds__(256, 2)
void qkv_gemm(const float* __restrict__ bk, const float* __restrict__ bv)
{
    extern __shared__ bf16 smem[];
    const int m0 = blockIdx.y << 7, n0 = blockIdx.x << 7;
    const int z = blockIdx.z;
    const bf16 *Ahi, *Alo, *Bh, *Bl;
    const float* bias;
    bf16 *Chi, *Clo;
    float scale;
    if (z == 0){
        Ahi = g_Xhi;  Alo = g_Xlo;  Bh = g_Wqthi; Bl = g_Wqtlo;
        bias = g_bq2; scale = 0.125f; Chi = g_qhi; Clo = g_qlo;
    } else if (z == 1){
        Ahi = g_hthi; Alo = g_htlo; Bh = g_Wkthi; Bl = g_Wktlo;
        bias = bk;    scale = 1.f;   Chi = g_khi; Clo = g_klo;
    } else {
        Ahi = g_hthi; Alo = g_htlo; Bh = g_Wvthi; Bl = g_Wvtlo;
        bias = bv;    scale = 1.f;   Chi = g_vhi; Clo = g_vlo;
    }

    GemmCtx c = gemm_ctx(smem);
    float acc[4][4][4] = {};
    const int nst = E_ >> 5;   // 24

    gemm_issue(smem, 0, 0, Ahi, Alo, E_, m0, Bh, Bl, E_, n0);
    gemm_issue(smem, 1, 32, Ahi, Alo, E_, m0, Bh, Bl, E_, n0);

    for (int s = 0; s < nst; s++){
        if (s + 1 < nst) CP_WAIT1(); else CP_WAIT0();
        __syncthreads();
        gemm_stage_mma(c, s, acc);
        __syncthreads();
        if (s + 2 < nst)
            gemm_issue(smem, s & 1, (s + 2) << 5, Ahi, Alo, E_, m0, Bh, Bl, E_, n0);
    }

    #pragma unroll
    for (int mt = 0; mt < 4; mt++){
        #pragma unroll
        for (int nt = 0; nt < 4; nt++){
            int ca = n0 + (c.wn << 5) + (nt << 3) + c.tg * 2;
            #pragma unroll
            for (int half = 0; half < 2; half++){
                int row = m0 + (c.wm << 6) + (mt << 4) + c.g + (half << 3);
                float v0 = (acc[mt][nt][half * 2]     + bias[ca])     * scale;
                float v1 = (acc[mt][nt][half * 2 + 1] + bias[ca + 1]) * scale;
                int bb = row >> 9, t = row & 511;
                int hh = ca >> 6, d = ca & 63;
                bf16 h0 = __float2bfloat16(v0);
                bf16 h1 = __float2bfloat16(v1);
                bf16 l0 = __float2bfloat16(v0 - __bfloat162float(h0));
                bf16 l1 = __float2bfloat16(v1 - __bfloat162float(h1));
                if (z <= 1){
                    size_t dst = (((size_t)bb * H_ + hh) * T_ + t) * 64 + d;
                    __nv_bfloat162 hp; hp.x = h0; hp.y = h1;
                    __nv_bfloat162 lp; lp.x = l0; lp.y = l1;
                    *(__nv_bfloat162*)(Chi + dst) = hp;
                    *(__nv_bfloat162*)(Clo + dst) = lp;
                } else {
                    size_t dst = (((size_t)bb * H_ + hh) * 64 + d) * T_ + t;
                    Chi[dst] = h0; Chi[dst + T_] = h1;
                    Clo[dst] = l0; Clo[dst + T_] = l1;
                }
            }
        }
    }
}

// ---------------- prep kernels ----------------
__global__ __launch_bounds__(256)
void split_kernel(const float* __restrict__ x, bf16* __restrict__ hi,
                  bf16* __restrict__ lo, int n)
{
    int i = blockIdx.x * 256 + threadIdx.x;
    if (i >= n) return;
    float v = x[i];
    bf16 h = __float2bfloat16(v);
    hi[i] = h;
    lo[i] = __float2bfloat16(v - __bfloat162float(h));
}

// all 4 weight transposes in one launch (grid.z selects)
__global__ __launch_bounds__(256)
void transW_all(const float* __restrict__ Wq, const float* __restrict__ Wk,
                const float* __restrict__ Wv, const float* __restrict__ Wo)
{
    __shared__ float t[32][33];
    const int z = blockIdx.z;
    const float* W = (z == 0) ? Wq : (z == 1) ? Wk : (z == 2) ? Wv : Wo;
    bf16* Thi = (z == 0) ? g_Wqthi : (z == 1) ? g_Wkthi : (z == 2) ? g_Wvthi : g_Wothi;
    bf16* Tlo = (z == 0) ? g_Wqtlo : (z == 1) ? g_Wktlo : (z == 2) ? g_Wvtlo : g_Wotlo;
    int k0 = blockIdx.x * 32, n0 = blockIdx.y * 32;
    int tx = threadIdx.x & 31, ty = threadIdx.x >> 5;   // 32x8
    #pragma unroll
    for (int i = 0; i < 4; i++)
        t[ty + 8 * i][tx] = W[(size_t)(k0 + ty + 8 * i) * E_ + n0 + tx];
    __syncthreads();
    #pragma unroll
    for (int i = 0; i < 4; i++){
        float v = t[tx][ty + 8 * i];
        size_t o = (size_t)(n0 + ty + 8 * i) * E_ + k0 + tx;
        bf16 h = __float2bfloat16(v);
        Thi[o] = h;
        Tlo[o] = __float2bfloat16(v - __bfloat162float(h));
    }
}

__global__ __launch_bounds__(256)
void tePad_kernel(const float* __restrict__ TE, bf16* __restrict__ hi,
                  bf16* __restrict__ lo)
{
    int i = blockIdx.x * 256 + threadIdx.x;    // over 128*768
    if (i >= 128 * E_) return;
    int l = i / E_, e = i % E_;
    float v = (l < L_) ? TE[(size_t)l * E_ + e] : 0.f;
    bf16 h = __float2bfloat16(v);
    hi[i] = h;
    lo[i] = __float2bfloat16(v - __bfloat162float(h));
}

__global__ __launch_bounds__(256)
void teT_kernel(const float* __restrict__ TE, bf16* __restrict__ hi,
                bf16* __restrict__ lo)
{
    int i = blockIdx.x * 256 + threadIdx.x;    // over 768*128
    if (i >= E_ * 128) return;
    int e = i >> 7, l = i & 127;
    float v = (l < L_) ? TE[(size_t)l * E_ + e] : 0.f;
    bf16 h = __float2bfloat16(v);
    hi[i] = h;
    lo[i] = __float2bfloat16(v - __bfloat162float(h));
}

// bq2 = bq + tp @ Wq, two-phase parallel reduction (deterministic)
__global__ __launch_bounds__(256)
void biasq_part(const float* __restrict__ tp, const float* __restrict__ Wq,
                float* __restrict__ part)
{
    int n = blockIdx.x * 256 + threadIdx.x;   // grid.x = 3
    int kc = blockIdx.y;                       // grid.y = 16
    float acc = 0.f;
    int k0 = kc * 48;
    #pragma unroll 8
    for (int k = k0; k < k0 + 48; k++)
        acc += tp[k] * Wq[(size_t)k * E_ + n];
    part[kc * E_ + n] = acc;
}
__global__ __launch_bounds__(256)
void biasq_reduce(const float* __restrict__ part, const float* __restrict__ bq,
                  float* __restrict__ out)
{
    int n = blockIdx.x * 256 + threadIdx.x;   // grid.x = 3
    float acc = bq[n];
    #pragma unroll
    for (int y = 0; y < 16; y++) acc += part[y * E_ + n];
    out[n] = acc;
}

// ---------------- softmax over L=100, writes bf16 split padded to 128 ----------------
__global__ __launch_bounds__(256)
void softmax100_kernel(const float* __restrict__ scores,
                       bf16* __restrict__ atthi, bf16* __restrict__ attlo)
{
    int warp = (blockIdx.x * blockDim.x + threadIdx.x) >> 5;
    int lane = threadIdx.x & 31;
    if (warp >= MROWS) return;
    const float* s = scores + (size_t)warp * L_;
    float v[4];
    float mx = -INFINITY;
    #pragma unroll
    for (int i = 0; i < 4; i++){
        int l = lane + i * 32;
        v[i] = (l < L_) ? s[l] : -INFINITY;
        mx = fmaxf(mx, v[i]);
    }
    #pragma unroll
    for (int w = 16; w; w >>= 1) mx = fmaxf(mx, __shfl_xor_sync(0xffffffffu, mx, w));
    float sum = 0.f;
    #pragma unroll
    for (int i = 0; i < 4; i++){
        int l = lane + i * 32;
        v[i] = (l < L_) ? expf(v[i] - mx) : 0.f;
        sum += v[i];
    }
    #pragma unroll
    for (int w = 16; w; w >>= 1) sum += __shfl_xor_sync(0xffffffffu, sum, w);
    float inv = 1.f / sum;
    #pragma unroll
    for (int i = 0; i < 4; i++){
        int l = lane + i * 32;
        float p = (l < L_) ? v[i] * inv : 0.f;
        bf16 h = __float2bfloat16(p);
        atthi[(size_t)warp * 128 + l] = h;
        attlo[(size_t)warp * 128 + l] = __float2bfloat16(p - __bfloat162float(h));
    }
}

// ---------------- tensor-core flash attention (split-bf16, LDSM) ----------------
#define FST 72   // flash smem row stride (bf16); 144B rows, LDSM conflict-free
__global__ __launch_bounds__(256, 2)
void flash_mma(const bf16* __restrict__ qh_g, const bf16* __restrict__ ql_g,
               const bf16* __restrict__ kh_g, const bf16* __restrict__ kl_g,
               const bf16* __restrict__ vh_g, const bf16* __restrict__ vl_g,
               const float* __restrict__ amask,
               bf16* __restrict__ ctxhi, bf16* __restrict__ ctxlo)
{
    extern __shared__ bf16 fs[];
    const int b = blockIdx.z, h = blockIdx.y, q0 = blockIdx.x << 7;
    const int tid = threadIdx.x, lane = tid & 31, w = tid >> 5;
    const int g = lane >> 2, tg = lane & 3;
    const int bh = b * H_ + h;

    bf16* sQh = fs;
    bf16* sQl = fs + 9216;           // 128*72
    float* sM = (float*)(fs + 55296);
    const uint32_t fs_u = smem_u32(fs);

    // mask bias into smem
    sM[tid]       = (1.f - amask[(size_t)b * T_ + tid])       * NEGBIG;
    sM[tid + 256] = (1.f - amask[(size_t)b * T_ + tid + 256]) * NEGBIG;

    // LDSM per-lane offsets (bytes)
    const uint32_t qoff = (uint32_t)(((w << 4) + (lane & 15)) * 144 + ((lane >> 4) << 4));
    const uint32_t koff = (uint32_t)((((lane >> 4) << 3) + (lane & 7)) * 144
                                     + (((lane >> 3) & 1) << 4));

    // issue Q (hi+lo): 128 rows x 8 chunks x 2 mats
    #pragma unroll
    for (int it = 0; it < 8; it++){
        int mat = it >> 2;
        int idx = tid + ((it & 3) << 8);
        int r = idx >> 3, c = idx & 7;
        const bf16* src = (mat ? ql_g : qh_g) + ((size_t)bh * T_ + q0 + r) * 64 + c * 8;
        cp16(smem_u32((mat ? sQl : sQh) + r * FST + c * 8), src);
    }
    CP_COMMIT();

    auto issueT = [&](int buf, int kt){
        #pragma unroll
        for (int it = 0; it < 8; it++){
            int mat = it >> 1;
            int idx = tid + ((it & 1) << 8);
            int r = idx >> 3, c = idx & 7;
            const bf16* src;
            if (mat == 0)      src = kh_g + ((size_t)bh * T_ + kt * 64 + r) * 64 + c * 8;
            else if (mat == 1) src = kl_g + ((size_t)bh * T_ + kt * 64 + r) * 64 + c * 8;
            else if (mat == 2) src = vh_g + ((size_t)bh * 64 + r) * T_ + kt * 64 + c * 8;
            else               src = vl_g + ((size_t)bh * 64 + r) * T_ + kt * 64 + c * 8;
            cp16(smem_u32(fs + 18432 + buf * 18432 + mat * 4608 + r * FST + c * 8), src);
        }
        CP_COMMIT();
    };
    issueT(0, 0);
    issueT(1, 1);
    CP_WAIT1();            // Q + tile0 done
    __syncthreads();

    // Q frags (register-resident, reused over all k-tiles)
    uint32_t qh[4][4], ql[4][4];
    #pragma unroll
    for (int kb = 0; kb < 4; kb++){
        ldsm4(qh[kb], fs_u + qoff + (uint32_t)(kb << 5));
        ldsm4(ql[kb], fs_u + 18432u + qoff + (uint32_t)(kb << 5));
    }

    const int qg0 = q0 + (w << 4) + g, qg1 = qg0 + 8;
    float o[8][4] = {};
    float mp0 = -INFINITY, mp1 = -INFINITY, l0 = 0.f, l1 = 0.f;

    for (int kt = 0; kt < 8; kt++){
        if (kt){
            if (kt < 7) CP_WAIT1(); else CP_WAIT0();
            __syncthreads();
        }
        const uint32_t Kh_u = fs_u + 36864u + (uint32_t)((kt & 1) * 36864);
        const uint32_t Kl_u = Kh_u + 9216u;
        const uint32_t Vh_u = Kh_u + 18432u;
        const uint32_t Vl_u = Kh_u + 27648u;

        // S = Q @ K^T  (128x64 per CTA; 16x64 per warp)
        float s[8][4] = {};
        #pragma unroll
        for (int np = 0; np < 4; np++){
            #pragma unroll
            for (int kb = 0; kb < 4; kb++){
                uint32_t k4h[4], k4l[4];
                uint32_t off = koff + (uint32_t)(np * 2304) + (uint32_t)(kb << 5);
                ldsm4(k4h, Kh_u + off);
                ldsm4(k4l, Kl_u + off);
                mma16816(s[2*np],     qh[kb], k4h);
                mma16816(s[2*np],     ql[kb], k4h);
                mma16816(s[2*np],     qh[kb], k4l);
                mma16816(s[2*np+1],   qh[kb], k4h + 2);
                mma16816(s[2*np+1],   ql[kb], k4h + 2);
                mma16816(s[2*np+1],   qh[kb], k4l + 2);
            }
        }

        // mask + online softmax
        float rm0 = -INFINITY, rm1 = -INFINITY;
        #pragma unroll
        for (int nf = 0; nf < 8; nf++){
            int cg = (kt << 6) + (nf << 3) + (tg << 1);
            float ma = sM[cg], mb = sM[cg + 1];
            s[nf][0] += ma + ((cg     == qg0) ? NEGBIG : 0.f);
            s[nf][1] += mb + ((cg + 1 == qg0) ? NEGBIG : 0.f);
            s[nf][2] += ma + ((cg     == qg1) ? NEGBIG : 0.f);
            s[nf][3] += mb + ((cg + 1 == qg1) ? NEGBIG : 0.f);
            rm0 = fmaxf(rm0, fmaxf(s[nf][0], s[nf][1]));
            rm1 = fmaxf(rm1, fmaxf(s[nf][2], s[nf][3]));
        }
        rm0 = fmaxf(rm0, __shfl_xor_sync(0xffffffffu, rm0, 1));
        rm0 = fmaxf(rm0, __shfl_xor_sync(0xffffffffu, rm0, 2));
        rm1 = fmaxf(rm1, __shfl_xor_sync(0xffffffffu, rm1, 1));
        rm1 = fmaxf(rm1, __shfl_xor_sync(0xffffffffu, rm1, 2));

        float mn0 = fmaxf(mp0, rm0), mn1 = fmaxf(mp1, rm1);
        float cf0 = __expf(mp0 - mn0), cf1 = __expf(mp1 - mn1);
        float rs0 = 0.f, rs1 = 0.f;
        #pragma unroll
        for (int nf = 0; nf < 8; nf++){
            s[nf][0] = __expf(s[nf][0] - mn0);
            s[nf][1] = __expf(s[nf][1] - mn0);
            s[nf][2] = __expf(s[nf][2] - mn1);
            s[nf][3] = __expf(s[nf][3] - mn1);
            rs0 += s[nf][0] + s[nf][1];
            rs1 += s[nf][2] + s[nf][3];
        }
        rs0 += __shfl_xor_sync(0xffffffffu, rs0, 1);
        rs0 += __shfl_xor_sync(0xffffffffu, rs0, 2);
        rs1 += __shfl_xor_sync(0xffffffffu, rs1, 1);
        rs1 += __shfl_xor_sync(0xffffffffu, rs1, 2);

        l0 = l0 * cf0 + rs0;
        l1 = l1 * cf1 + rs1;
        mp0 = mn0; mp1 = mn1;
        #pragma unroll
        for (int df = 0; df < 8; df++){
            o[df][0] *= cf0; o[df][1] *= cf0;
            o[df][2] *= cf1; o[df][3] *= cf1;
        }

        // O += P @ V   (P-hi only; dropped P-lo x V-hi term, ~1e-4 final rel err)
        #pragma unroll
        for (int kb = 0; kb < 4; kb++){
            uint32_t ph[4];
            ph[0] = pack2hi(s[2*kb][0],   s[2*kb][1]);
            ph[1] = pack2hi(s[2*kb][2],   s[2*kb][3]);
            ph[2] = pack2hi(s[2*kb+1][0], s[2*kb+1][1]);
            ph[3] = pack2hi(s[2*kb+1][2], s[2*kb+1][3]);
            #pragma unroll
            for (int dp = 0; dp < 4; dp++){
                uint32_t v4h[4], v4l[4];
                uint32_t off = koff + (uint32_t)(dp * 2304) + (uint32_t)(kb << 5);
                ldsm4(v4h, Vh_u + off);
                ldsm4(v4l, Vl_u + off);
                mma16816(o[2*dp],   ph, v4h);
                mma16816(o[2*dp],   ph, v4l);
                mma16816(o[2*dp+1], ph, v4h + 2);
                mma16816(o[2*dp+1], ph, v4l + 2);
            }
        }

        __syncthreads();
        if (kt + 2 < 8) issueT(kt & 1, kt + 2);
    }

    // write ctx (bf16 split) as [b*t, e] rows for the O-projection GEMM
    float i0 = 1.f / l0, i1 = 1.f / l1;
    size_t row0 = (size_t)b * T_ + qg0;
    size_t row1 = (size_t)b * T_ + qg1;
    #pragma unroll
    for (int df = 0; df < 8; df++){
        int d = h * 64 + (df << 3) + (tg << 1);
        uint32_t hp, lp;
        pack2(o[df][0] * i0, o[df][1] * i0, hp, lp);
        *(uint32_t*)(ctxhi + row0 * E_ + d) = hp;
        *(uint32_t*)(ctxlo + row0 * E_ + d) = lp;
        pack2(o[df][2] * i1, o[df][3] * i1, hp, lp);
        *(uint32_t*)(ctxhi + row1 * E_ + d) = hp;
        *(uint32_t*)(ctxlo + row1 * E_ + d) = lp;
    }
}

// ---------------- LayerNorm + final residual ----------------
__global__ __launch_bounds__(256)
void ln_kernel(const float* __restrict__ z, const float* __restrict__ g,
               const float* __restrict__ bb, const float* __restrict__ ht,
               float* __restrict__ out)
{
    const int m = blockIdx.x;
    const int t = threadIdx.x;
    __shared__ float buf[E_];
    __shared__ float red[8];
    const int lane = t & 31, wrp = t >> 5;

    float s = 0.f;
    for (int e = t; e < E_; e += 256){
        float x = z[(size_t)m * E_ + e];
        buf[e] = x;
        s += x;
    }
    #pragma unroll
    for (int w = 16; w; w >>= 1) s += __shfl_xor_sync(0xffffffffu, s, w);
    if (lane == 0) red[wrp] = s;
    __syncthreads();
    float mu = 0.f;
    #pragma unroll
    for (int i = 0; i < 8; i++) mu += red[i];
    mu *= (1.f / E_);
    __syncthreads();

    float vs = 0.f;
    for (int e = t; e < E_; e += 256){
        float d = buf[e] - mu;
        vs += d * d;
    }
    #pragma unroll
    for (int w = 16; w; w >>= 1) vs += __shfl_xor_sync(0xffffffffu, vs, w);
    if (lane == 0) red[wrp] = vs;
    __syncthreads();
    float var = 0.f;
    #pragma unroll
    for (int i = 0; i < 8; i++) var += red[i];
    var *= (1.f / E_);
    float rs = rsqrtf(var + 1e-12f);

    for (int e = t; e < E_; e += 256){
        out[(size_t)m * E_ + e] =
            (buf[e] - mu) * rs * g[e] + bb[e] + ht[(size_t)m * E_ + e];
    }
}

// ---------------- launch ----------------
extern "C" void kernel_launch(void* const* d_in, const int* in_sizes, int n_in,
                              void* d_out, int out_size)
{
    const float* X    = (const float*)d_in[0];
    const float* amsk = (const float*)d_in[1];
    const float* TE   = (const float*)d_in[2];
    const float* tp   = (const float*)d_in[3];
    const float* Wq   = (const float*)d_in[4];
    const float* bq   = (const float*)d_in[5];
    const float* Wk   = (const float*)d_in[6];
    const float* bk   = (const float*)d_in[7];
    const float* Wv   = (const float*)d_in[8];
    const float* bv   = (const float*)d_in[9];
    const float* Wo   = (const float*)d_in[10];
    const float* bo   = (const float*)d_in[11];
    const float* lng  = (const float*)d_in[12];
    const float* lnb  = (const float*)d_in[13];

    float* out    = (float*)d_out;
    float* scores = out + (size_t)MROWS * E_;

    bf16 *pXhi, *pXlo, *patthi, *pattlo, *phthi, *phtlo, *pctxhi, *pctxlo;
    bf16 *pqhi, *pqlo, *pkhi, *pklo, *pvhi, *pvlo;
    bf16 *pWo1, *pWo2;
    bf16 *pTE1, *pTE2, *pTEt1, *pTEt2;
    float *pht, *pz, *pbq2, *pbqpart;
    cudaGetSymbolAddress((void**)&pXhi,   g_Xhi);
    cudaGetSymbolAddress((void**)&pXlo,   g_Xlo);
    cudaGetSymbolAddress((void**)&patthi, g_atthi);
    cudaGetSymbolAddress((void**)&pattlo, g_attlo);
    cudaGetSymbolAddress((void**)&pht,    g_ht);
    cudaGetSymbolAddress((void**)&phthi,  g_hthi);
    cudaGetSymbolAddress((void**)&phtlo,  g_htlo);
    cudaGetSymbolAddress((void**)&pqhi,   g_qhi);
    cudaGetSymbolAddress((void**)&pqlo,   g_qlo);
    cudaGetSymbolAddress((void**)&pkhi,   g_khi);
    cudaGetSymbolAddress((void**)&pklo,   g_klo);
    cudaGetSymbolAddress((void**)&pvhi,   g_vhi);
    cudaGetSymbolAddress((void**)&pvlo,   g_vlo);
    cudaGetSymbolAddress((void**)&pctxhi, g_ctxhi);
    cudaGetSymbolAddress((void**)&pctxlo, g_ctxlo);
    cudaGetSymbolAddress((void**)&pz,     g_z);
    cudaGetSymbolAddress((void**)&pWo1,   g_Wothi);
    cudaGetSymbolAddress((void**)&pWo2,   g_Wotlo);
    cudaGetSymbolAddress((void**)&pTE1,   g_TEhi);
    cudaGetSymbolAddress((void**)&pTE2,   g_TElo);
    cudaGetSymbolAddress((void**)&pTEt1,  g_TEthi);
    cudaGetSymbolAddress((void**)&pTEt2,  g_TEtlo);
    cudaGetSymbolAddress((void**)&pbq2,   g_bq2);
    cudaGetSymbolAddress((void**)&pbqpart, g_bqpart);

    const int gsm = 2 * (int)GSTG_BYTES;   // 81920
    cudaFuncSetAttribute(mma_gemm<0>, cudaFuncAttributeMaxDynamicSharedMemorySize, gsm);
    cudaFuncSetAttribute(mma_gemm<2>, cudaFuncAttributeMaxDynamicSharedMemorySize, gsm);
    cudaFuncSetAttribute(mma_gemm<3>, cudaFuncAttributeMaxDynamicSharedMemorySize, gsm);
    cudaFuncSetAttribute(qkv_gemm,    cudaFuncAttributeMaxDynamicSharedMemorySize, gsm);
    const int fsm_bytes = 55296 * (int)sizeof(bf16) + 512 * (int)sizeof(float); // 112640
    cudaFuncSetAttribute(flash_mma, cudaFuncAttributeMaxDynamicSharedMemorySize,
                         fsm_bytes);

    dim3 blk(256);

    // ---- prep + compute, scores GEMM kept at launch index 3 for profiling ----
    split_kernel<<<(MROWS * E_ + 255) / 256, blk>>>(X, pXhi, pXlo, MROWS * E_);     // 0
    transW_all<<<dim3(24, 24, 4), blk>>>(Wq, Wk, Wv, Wo);                            // 1
    tePad_kernel<<<(128 * E_ + 255) / 256, blk>>>(TE, pTE1, pTE2);                   // 2
    // ---- scores = X @ TE^T ----                                                    3  (profiled)
    mma_gemm<0><<<dim3(1, 64), blk, gsm>>>(pXhi, pXlo, E_, pTE1, pTE2, E_, E_,
                                           nullptr, nullptr, nullptr,
                                           scores, nullptr, nullptr);
    // ---- att = softmax(scores) ----                                                4
    softmax100_kernel<<<MROWS / 8, blk>>>(scores, patthi, pattlo);
    teT_kernel<<<(E_ * 128 + 255) / 256, blk>>>(TE, pTEt1, pTEt2);                   // 5
    biasq_part<<<dim3(3, 16), blk>>>(tp, Wq, pbqpart);                               // 6
    biasq_reduce<<<3, blk>>>(pbqpart, bq, pbq2);                                     // 7
    // ---- h_truth = att @ TE + X (fp32 + bf16 split) ----                           8
    mma_gemm<2><<<dim3(6, 64), blk, gsm>>>(patthi, pattlo, 128, pTEt1, pTEt2, 128, 128,
                                           nullptr, X, nullptr,
                                           pht, phthi, phtlo);
    // ---- q,k,v fused ----                                                          9
    qkv_gemm<<<dim3(6, 64, 3), blk, gsm>>>(bk, bv);
    // ---- flash attention ----                                                     10
    flash_mma<<<dim3(4, H_, B_), blk, fsm_bytes>>>(pqhi, pqlo, pkhi, pklo,
                                                   pvhi, pvlo, amsk,
                                                   pctxhi, pctxlo);
    // ---- z = ctx @ Wo + bo + X + tp ----                                          11
    mma_gemm<3><<<dim3(6, 64), blk, gsm>>>(pctxhi, pctxlo, E_, pWo1, pWo2, E_, E_,
                                           bo, X, tp,
                                           pz, nullptr, nullptr);
    // ---- out = LN(z) + h_truth ----                                               12
    ln_kernel<<<MROWS, blk>>>(pz, lng, lnb, pht, out);
}

// round 16
// speedup vs baseline: 1.1247x; 1.0239x over previous
#include <cuda_runtime.h>
#include <cuda_bf16.h>
#include <cstdint>
#include <cstddef>

#define B_ 16
#define T_ 512
#define E_ 768
#define H_ 12
#define D_ 64
#define L_ 100
#define MROWS (B_*T_)   // 8192
#define NEGBIG (-1e9f)
typedef __nv_bfloat16 bf16;

// ---------------- scratch (__device__ globals; alloc-free rule) ----------------
__device__ bf16 g_Xhi[MROWS*E_], g_Xlo[MROWS*E_];
__device__ bf16 g_atthi[MROWS*128], g_attlo[MROWS*128];
__device__ float g_ht[MROWS*E_];
__device__ bf16 g_hthi[MROWS*E_], g_htlo[MROWS*E_];
__device__ bf16 g_qhi[MROWS*E_], g_qlo[MROWS*E_];   // [b,h,t,d]
__device__ bf16 g_khi[MROWS*E_], g_klo[MROWS*E_];   // [b,h,t,d]
__device__ bf16 g_vhi[MROWS*E_], g_vlo[MROWS*E_];   // [b,h,d,t]
__device__ bf16 g_ctxhi[MROWS*E_], g_ctxlo[MROWS*E_];
__device__ float g_z[MROWS*E_];
__device__ bf16 g_Wqthi[E_*E_], g_Wqtlo[E_*E_];
__device__ bf16 g_Wkthi[E_*E_], g_Wktlo[E_*E_];
__device__ bf16 g_Wvthi[E_*E_], g_Wvtlo[E_*E_];
__device__ bf16 g_Wothi[E_*E_], g_Wotlo[E_*E_];
__device__ bf16 g_TEhi[128*E_], g_TElo[128*E_];
__device__ bf16 g_TEthi[E_*128], g_TEtlo[E_*128];
__device__ float g_bq2[E_];
__device__ float g_bqpart[16*E_];
__device__ float g_scpart[2*MROWS*128];   // split-K partials for scores

// ---------------- helpers ----------------
__device__ __forceinline__ uint32_t smem_u32(const void* p){
    uint32_t a;
    asm("{ .reg .u64 t; cvta.to.shared.u64 t, %1; cvt.u32.u64 %0, t; }":"=r"(a):"l"(p));
    return a;
}
__device__ __forceinline__ void cp16(uint32_t dst, const void* src){
    asm volatile("cp.async.cg.shared.global [%0], [%1], 16;" :: "r"(dst), "l"(src));
}
#define CP_COMMIT() asm volatile("cp.async.commit_group;":::"memory")
#define CP_WAIT1()  asm volatile("cp.async.wait_group 1;":::"memory")
#define CP_WAIT0()  asm volatile("cp.async.wait_group 0;":::"memory")

__device__ __forceinline__ void mma16816(float* c, const uint32_t* a, const uint32_t* b){
    asm volatile(
        "mma.sync.aligned.m16n8k16.row.col.f32.bf16.bf16.f32 "
        "{%0,%1,%2,%3}, {%4,%5,%6,%7}, {%8,%9}, {%0,%1,%2,%3};"
        : "+f"(c[0]), "+f"(c[1]), "+f"(c[2]), "+f"(c[3])
        : "r"(a[0]), "r"(a[1]), "r"(a[2]), "r"(a[3]), "r"(b[0]), "r"(b[1]));
}
__device__ __forceinline__ void ldsm4(uint32_t* r, uint32_t addr){
    asm volatile("ldmatrix.sync.aligned.m8n8.x4.shared.b16 {%0,%1,%2,%3}, [%4];"
        : "=r"(r[0]), "=r"(r[1]), "=r"(r[2]), "=r"(r[3]) : "r"(addr));
}

__device__ __forceinline__ void pack2(float a, float b, uint32_t& hi, uint32_t& lo){
    bf16 ha = __float2bfloat16(a), hb = __float2bfloat16(b);
    bf16 la = __float2bfloat16(a - __bfloat162float(ha));
    bf16 lb = __float2bfloat16(b - __bfloat162float(hb));
    __nv_bfloat162 hp; hp.x = ha; hp.y = hb;
    __nv_bfloat162 lp; lp.x = la; lp.y = lb;
    hi = *(uint32_t*)&hp;
    lo = *(uint32_t*)&lp;
}
__device__ __forceinline__ uint32_t pack2hi(float a, float b){
    __nv_bfloat162 hp;
    hp.x = __float2bfloat16(a);
    hp.y = __float2bfloat16(b);
    return *(uint32_t*)&hp;
}

#define AST 40   // GEMM smem row stride (bf16); 80B rows, LDSM conflict-free
// 128x128 tile, stage = 4 mats x 128*AST bf16 = 40960 bytes
#define GSTG_BYTES 40960u

// ---- GEMM core context (128x128 CTA tile, 8 warps of 64x32) ----
struct GemmCtx {
    uint32_t fs_u, aoff, boff;
    int wm, wn, g, tg;
};
__device__ __forceinline__ GemmCtx gemm_ctx(const bf16* smem){
    GemmCtx c;
    int tid = threadIdx.x;
    int lane = tid & 31, wid = tid >> 5;
    c.wm = wid & 1; c.wn = wid >> 1;
    c.g = lane >> 2; c.tg = lane & 3;
    c.fs_u = smem_u32(smem);
    c.aoff = (uint32_t)(((c.wm << 6) + (lane & 15)) * 80 + ((lane >> 4) << 4));
    c.boff = (uint32_t)(((c.wn << 5) + ((lane >> 4) << 3) + (lane & 7)) * 80
                        + (((lane >> 3) & 1) << 4));
    return c;
}

// issue one k32 stage: A/B 128 rows each, hi+lo
__device__ __forceinline__ void gemm_issue(bf16* smem, int st, int k0,
    const bf16* __restrict__ Ahi, const bf16* __restrict__ Alo, int lda, int m0,
    const bf16* __restrict__ Bhi, const bf16* __restrict__ Blo, int ldb, int n0)
{
    const int tid = threadIdx.x;
    bf16* base = smem + st * 20480;   // 40960 bytes / 2
    const bf16* srcs[4] = {Ahi, Alo, Bhi, Blo};
    const int   lds_[4] = {lda, lda, ldb, ldb};
    const int   r0s_[4] = {m0, m0, n0, n0};
    #pragma unroll
    for (int mat = 0; mat < 4; mat++){
        bf16* dstm = base + mat * 5120;
        #pragma unroll
        for (int it = 0; it < 2; it++){
            int idx = tid + (it << 8);
            int r = idx >> 2, c = idx & 3;
            cp16(smem_u32(dstm + r * AST + c * 8),
                 srcs[mat] + (size_t)(r0s_[mat] + r) * lds_[mat] + k0 + c * 8);
        }
    }
    CP_COMMIT();
}

__device__ __forceinline__ void gemm_stage_mma(const GemmCtx& c, int s, float acc[4][4][4]){
    const uint32_t stg = c.fs_u + (uint32_t)((s & 1) * GSTG_BYTES);
    #pragma unroll
    for (int kh = 0; kh < 2; kh++){
        const uint32_t kb32 = (uint32_t)(kh << 5);
        uint32_t bfh[8], bfl[8];
        ldsm4(bfh,     stg + 20480u + c.boff + kb32);
        ldsm4(bfh + 4, stg + 20480u + c.boff + 1280u + kb32);
        ldsm4(bfl,     stg + 30720u + c.boff + kb32);
        ldsm4(bfl + 4, stg + 30720u + c.boff + 1280u + kb32);
        #pragma unroll
        for (int mt = 0; mt < 4; mt++){
            uint32_t ah[4], al[4];
            ldsm4(ah, stg + c.aoff + (uint32_t)(mt * 1280) + kb32);
            ldsm4(al, stg + 10240u + c.aoff + (uint32_t)(mt * 1280) + kb32);
            #pragma unroll
            for (int nt = 0; nt < 4; nt++){
                mma16816(acc[mt][nt], ah, bfh + nt * 2);
                mma16816(acc[mt][nt], al, bfh + nt * 2);
                mma16816(acc[mt][nt], ah, bfl + nt * 2);
            }
        }
    }
}

// ---------------- split-bf16 HMMA GEMM: C[M,N] = A @ B^T (+epilogue) ----------------
// EPI: 2 = +Xres, store fp32 C and bf16 split Chi/Clo   (h_truth)
//      3 = +bias +Xres +tp, store fp32                  (z)
//      4 = split-K partial: raw acc to C[z][M][128]     (scores halves)
template<int EPI>
__global__ __launch_bounds__(256, 2)
void mma_gemm(const bf16* __restrict__ Ahi, const bf16* __restrict__ Alo, int lda,
              const bf16* __restrict__ Bhi, const bf16* __restrict__ Blo, int ldb,
              int K,
              const float* __restrict__ bias, const float* __restrict__ Xres,
              const float* __restrict__ tp,
              float* __restrict__ C,
              bf16* __restrict__ Chi, bf16* __restrict__ Clo)
{
    extern __shared__ bf16 smem[];
    const int m0 = blockIdx.y << 7, n0 = blockIdx.x << 7;
    if (EPI == 4){
        int koff = blockIdx.z * K;    // K = half-length for split-K
        Ahi += koff; Alo += koff; Bhi += koff; Blo += koff;
    }
    GemmCtx c = gemm_ctx(smem);
    float acc[4][4][4] = {};
    const int nst = K >> 5;

    gemm_issue(smem, 0, 0, Ahi, Alo, lda, m0, Bhi, Blo, ldb, n0);
    if (nst > 1) gemm_issue(smem, 1, 32, Ahi, Alo, lda, m0, Bhi, Blo, ldb, n0);

    for (int s = 0; s < nst; s++){
        if (s + 1 < nst) CP_WAIT1(); else CP_WAIT0();
        __syncthreads();
        gemm_stage_mma(c, s, acc);
        __syncthreads();
        if (s + 2 < nst)
            gemm_issue(smem, s & 1, (s + 2) << 5, Ahi, Alo, lda, m0, Bhi, Blo, ldb, n0);
    }

    // epilogue
    #pragma unroll
    for (int mt = 0; mt < 4; mt++){
        #pragma unroll
        for (int nt = 0; nt < 4; nt++){
            int ca = n0 + (c.wn << 5) + (nt << 3) + c.tg * 2;
            #pragma unroll
            for (int half = 0; half < 2; half++){
                int row = m0 + (c.wm << 6) + (mt << 4) + c.g + (half << 3);
                float v0 = acc[mt][nt][half * 2];
                float v1 = acc[mt][nt][half * 2 + 1];
                if (EPI == 4){
                    size_t o = ((size_t)(blockIdx.z * MROWS) + row) * 128 + ca;
                    float2 f2; f2.x = v0; f2.y = v1;
                    *(float2*)(C + o) = f2;
                } else {
                    size_t o = (size_t)row * E_ + ca;
                    if (EPI == 3){ v0 += bias[ca]; v1 += bias[ca + 1]; }
                    v0 += Xres[o]; v1 += Xres[o + 1];
                    if (EPI == 3){ v0 += tp[ca]; v1 += tp[ca + 1]; }
                    float2 f2; f2.x = v0; f2.y = v1;
                    *(float2*)(C + o) = f2;
                    if (EPI == 2){
                        uint32_t hp, lp;
                        pack2(v0, v1, hp, lp);
                        *(uint32_t*)(Chi + o) = hp;
                        *(uint32_t*)(Clo + o) = lp;
                    }
                }
            }
        }
    }
}

// sum the two split-K halves into scores [MROWS, 100]
__global__ __launch_bounds__(256)
void scores_reduce(const float* __restrict__ part, float* __restrict__ scores)
{
    int idx = blockIdx.x * 256 + threadIdx.x;
    if (idx >= MROWS * L_) return;
    int m = idx / L_, l = idx - m * L_;
    scores[idx] = part[(size_t)m * 128 + l] + part[(size_t)(MROWS + m) * 128 + l];
}

// ---------------- fused q/k/v projection (grid.z selects operand set) ----------------
__global__ __launch_bounds__(256, 2)
void qkv_gemm(const float* __restrict__ bk, const float* __restrict__ bv)
{
    extern __shared__ bf16 smem[];
    const int m0 = blockIdx.y << 7, n0 = blockIdx.x << 7;
    const int z = blockIdx.z;
    const bf16 *Ahi, *Alo, *Bh, *Bl;
    const float* bias;
    bf16 *Chi, *Clo;
    float scale;
    if (z == 0){
        Ahi = g_Xhi;  Alo = g_Xlo;  Bh = g_Wqthi; Bl = g_Wqtlo;
        bias = g_bq2; scale = 0.125f; Chi = g_qhi; Clo = g_qlo;
    } else if (z == 1){
        Ahi = g_hthi; Alo = g_htlo; Bh = g_Wkthi; Bl = g_Wktlo;
        bias = bk;    scale = 1.f;   Chi = g_khi; Clo = g_klo;
    } else {
        Ahi = g_hthi; Alo = g_htlo; Bh = g_Wvthi; Bl = g_Wvtlo;
        bias = bv;    scale = 1.f;   Chi = g_vhi; Clo = g_vlo;
    }

    GemmCtx c = gemm_ctx(smem);
    float acc[4][4][4] = {};
    const int nst = E_ >> 5;   // 24

    gemm_issue(smem, 0, 0, Ahi, Alo, E_, m0, Bh, Bl, E_, n0);
    gemm_issue(smem, 1, 32, Ahi, Alo, E_, m0, Bh, Bl, E_, n0);

    for (int s = 0; s < nst; s++){
        if (s + 1 < nst) CP_WAIT1(); else CP_WAIT0();
        __syncthreads();
        gemm_stage_mma(c, s, acc);
        __syncthreads();
        if (s + 2 < nst)
            gemm_issue(smem, s & 1, (s + 2) << 5, Ahi, Alo, E_, m0, Bh, Bl, E_, n0);
    }

    #pragma unroll
    for (int mt = 0; mt < 4; mt++){
        #pragma unroll
        for (int nt = 0; nt < 4; nt++){
            int ca = n0 + (c.wn << 5) + (nt << 3) + c.tg * 2;
            #pragma unroll
            for (int half = 0; half < 2; half++){
                int row = m0 + (c.wm << 6) + (mt << 4) + c.g + (half << 3);
                float v0 = (acc[mt][nt][half * 2]     + bias[ca])     * scale;
                float v1 = (acc[mt][nt][half * 2 + 1] + bias[ca + 1]) * scale;
                int bb = row >> 9, t = row & 511;
                int hh = ca >> 6, d = ca & 63;
                bf16 h0 = __float2bfloat16(v0);
                bf16 h1 = __float2bfloat16(v1);
                bf16 l0 = __float2bfloat16(v0 - __bfloat162float(h0));
                bf16 l1 = __float2bfloat16(v1 - __bfloat162float(h1));
                if (z <= 1){
                    size_t dst = (((size_t)bb * H_ + hh) * T_ + t) * 64 + d;
                    __nv_bfloat162 hp; hp.x = h0; hp.y = h1;
                    __nv_bfloat162 lp; lp.x = l0; lp.y = l1;
                    *(__nv_bfloat162*)(Chi + dst) = hp;
                    *(__nv_bfloat162*)(Clo + dst) = lp;
                } else {
                    size_t dst = (((size_t)bb * H_ + hh) * 64 + d) * T_ + t;
                    Chi[dst] = h0; Chi[dst + T_] = h1;
                    Clo[dst] = l0; Clo[dst + T_] = l1;
                }
            }
        }
    }
}

// ---------------- prep kernels ----------------
__global__ __launch_bounds__(256)
void split_kernel(const float* __restrict__ x, bf16* __restrict__ hi,
                  bf16* __restrict__ lo, int n)
{
    int i = blockIdx.x * 256 + threadIdx.x;
    if (i >= n) return;
    float v = x[i];
    bf16 h = __float2bfloat16(v);
    hi[i] = h;
    lo[i] = __float2bfloat16(v - __bfloat162float(h));
}

// all 4 weight transposes in one launch (grid.z selects)
__global__ __launch_bounds__(256)
void transW_all(const float* __restrict__ Wq, const float* __restrict__ Wk,
                const float* __restrict__ Wv, const float* __restrict__ Wo)
{
    __shared__ float t[32][33];
    const int z = blockIdx.z;
    const float* W = (z == 0) ? Wq : (z == 1) ? Wk : (z == 2) ? Wv : Wo;
    bf16* Thi = (z == 0) ? g_Wqthi : (z == 1) ? g_Wkthi : (z == 2) ? g_Wvthi : g_Wothi;
    bf16* Tlo = (z == 0) ? g_Wqtlo : (z == 1) ? g_Wktlo : (z == 2) ? g_Wvtlo : g_Wotlo;
    int k0 = blockIdx.x * 32, n0 = blockIdx.y * 32;
    int tx = threadIdx.x & 31, ty = threadIdx.x >> 5;   // 32x8
    #pragma unroll
    for (int i = 0; i < 4; i++)
        t[ty + 8 * i][tx] = W[(size_t)(k0 + ty + 8 * i) * E_ + n0 + tx];
    __syncthreads();
    #pragma unroll
    for (int i = 0; i < 4; i++){
        float v = t[tx][ty + 8 * i];
        size_t o = (size_t)(n0 + ty + 8 * i) * E_ + k0 + tx;
        bf16 h = __float2bfloat16(v);
        Thi[o] = h;
        Tlo[o] = __float2bfloat16(v - __bfloat162float(h));
    }
}

__global__ __launch_bounds__(256)
void tePad_kernel(const float* __restrict__ TE, bf16* __restrict__ hi,
                  bf16* __restrict__ lo)
{
    int i = blockIdx.x * 256 + threadIdx.x;    // over 128*768
    if (i >= 128 * E_) return;
    int l = i / E_, e = i % E_;
    float v = (l < L_) ? TE[(size_t)l * E_ + e] : 0.f;
    bf16 h = __float2bfloat16(v);
    hi[i] = h;
    lo[i] = __float2bfloat16(v - __bfloat162float(h));
}

__global__ __launch_bounds__(256)
void teT_kernel(const float* __restrict__ TE, bf16* __restrict__ hi,
                bf16* __restrict__ lo)
{
    int i = blockIdx.x * 256 + threadIdx.x;    // over 768*128
    if (i >= E_ * 128) return;
    int e = i >> 7, l = i & 127;
    float v = (l < L_) ? TE[(size_t)l * E_ + e] : 0.f;
    bf16 h = __float2bfloat16(v);
    hi[i] = h;
    lo[i] = __float2bfloat16(v - __bfloat162float(h));
}

// bq2 = bq + tp @ Wq, two-phase parallel reduction (deterministic)
__global__ __launch_bounds__(256)
void biasq_part(const float* __restrict__ tp, const float* __restrict__ Wq,
                float* __restrict__ part)
{
    int n = blockIdx.x * 256 + threadIdx.x;   // grid.x = 3
    int kc = blockIdx.y;                       // grid.y = 16
    float acc = 0.f;
    int k0 = kc * 48;
    #pragma unroll 8
    for (int k = k0; k < k0 + 48; k++)
        acc += tp[k] * Wq[(size_t)k * E_ + n];
    part[kc * E_ + n] = acc;
}
__global__ __launch_bounds__(256)
void biasq_reduce(const float* __restrict__ part, const float* __restrict__ bq,
                  float* __restrict__ out)
{
    int n = blockIdx.x * 256 + threadIdx.x;   // grid.x = 3
    float acc = bq[n];
    #pragma unroll
    for (int y = 0; y < 16; y++) acc += part[y * E_ + n];
    out[n] = acc;
}

// ---------------- softmax over L=100, writes bf16 split padded to 128 ----------------
__global__ __launch_bounds__(256)
void softmax100_kernel(const float* __restrict__ scores,
                       bf16* __restrict__ atthi, bf16* __restrict__ attlo)
{
    int warp = (blockIdx.x * blockDim.x + threadIdx.x) >> 5;
    int lane = threadIdx.x & 31;
    if (warp >= MROWS) return;
    const float* s = scores + (size_t)warp * L_;
    float v[4];
    float mx = -INFINITY;
    #pragma unroll
    for (int i = 0; i < 4; i++){
        int l = lane + i * 32;
        v[i] = (l < L_) ? s[l] : -INFINITY;
        mx = fmaxf(mx, v[i]);
    }
    #pragma unroll
    for (int w = 16; w; w >>= 1) mx = fmaxf(mx, __shfl_xor_sync(0xffffffffu, mx, w));
    float sum = 0.f;
    #pragma unroll
    for (int i = 0; i < 4; i++){
        int l = lane + i * 32;
        v[i] = (l < L_) ? expf(v[i] - mx) : 0.f;
        sum += v[i];
    }
    #pragma unroll
    for (int w = 16; w; w >>= 1) sum += __shfl_xor_sync(0xffffffffu, sum, w);
    float inv = 1.f / sum;
    #pragma unroll
    for (int i = 0; i < 4; i++){
        int l = lane + i * 32;
        float p = (l < L_) ? v[i] * inv : 0.f;
        bf16 h = __float2bfloat16(p);
        atthi[(size_t)warp * 128 + l] = h;
        attlo[(size_t)warp * 128 + l] = __float2bfloat16(p - __bfloat162float(h));
    }
}

// ---------------- tensor-core flash attention (split-bf16, LDSM) ----------------
#define FST 72   // flash smem row stride (bf16); 144B rows, LDSM conflict-free
__global__ __launch_bounds__(256, 2)
void flash_mma(const bf16* __restrict__ qh_g, const bf16* __restrict__ ql_g,
               const bf16* __restrict__ kh_g, const bf16* __restrict__ kl_g,
               const bf16* __restrict__ vh_g, const bf16* __restrict__ vl_g,
               const float* __restrict__ amask,
               bf16* __restrict__ ctxhi, bf16* __restrict__ ctxlo)
{
    extern __shared__ bf16 fs[];
    const int b = blockIdx.z, h = blockIdx.y, q0 = blockIdx.x << 7;
    const int tid = threadIdx.x, lane = tid & 31, w = tid >> 5;
    const int g = lane >> 2, tg = lane & 3;
    const int bh = b * H_ + h;

    bf16* sQh = fs;
    bf16* sQl = fs + 9216;           // 128*72
    float* sM = (float*)(fs + 55296);
    const uint32_t fs_u = smem_u32(fs);

    // mask bias into smem
    sM[tid]       = (1.f - amask[(size_t)b * T_ + tid])       * NEGBIG;
    sM[tid + 256] = (1.f - amask[(size_t)b * T_ + tid + 256]) * NEGBIG;

    // LDSM per-lane offsets (bytes)
    const uint32_t qoff = (uint32_t)(((w << 4) + (lane & 15)) * 144 + ((lane >> 4) << 4));
    const uint32_t koff = (uint32_t)((((lane >> 4) << 3) + (lane & 7)) * 144
                                     + (((lane >> 3) & 1) << 4));

    // issue Q (hi+lo): 128 rows x 8 chunks x 2 mats
    #pragma unroll
    for (int it = 0; it < 8; it++){
        int mat = it >> 2;
        int idx = tid + ((it & 3) << 8);
        int r = idx >> 3, c = idx & 7;
        const bf16* src = (mat ? ql_g : qh_g) + ((size_t)bh * T_ + q0 + r) * 64 + c * 8;
        cp16(smem_u32((mat ? sQl : sQh) + r * FST + c * 8), src);
    }
    CP_COMMIT();

    auto issueT = [&](int buf, int kt){
        #pragma unroll
        for (int it = 0; it < 8; it++){
            int mat = it >> 1;
            int idx = tid + ((it & 1) << 8);
            int r = idx >> 3, c = idx & 7;
            const bf16* src;
            if (mat == 0)      src = kh_g + ((size_t)bh * T_ + kt * 64 + r) * 64 + c * 8;
            else if (mat == 1) src = kl_g + ((size_t)bh * T_ + kt * 64 + r) * 64 + c * 8;
            else if (mat == 2) src = vh_g + ((size_t)bh * 64 + r) * T_ + kt * 64 + c * 8;
            else               src = vl_g + ((size_t)bh * 64 + r) * T_ + kt * 64 + c * 8;
            cp16(smem_u32(fs + 18432 + buf * 18432 + mat * 4608 + r * FST + c * 8), src);
        }
        CP_COMMIT();
    };
    issueT(0, 0);
    issueT(1, 1);
    CP_WAIT1();            // Q + tile0 done
    __syncthreads();

    // Q frags (register-resident, reused over all k-tiles)
    uint32_t qh[4][4], ql[4][4];
    #pragma unroll
    for (int kb = 0; kb < 4; kb++){
        ldsm4(qh[kb], fs_u + qoff + (uint32_t)(kb << 5));
        ldsm4(ql[kb], fs_u + 18432u + qoff + (uint32_t)(kb << 5));
    }

    const int qg0 = q0 + (w << 4) + g, qg1 = qg0 + 8;
    float o[8][4] = {};
    float mp0 = -INFINITY, mp1 = -INFINITY, l0 = 0.f, l1 = 0.f;

    for (int kt = 0; kt < 8; kt++){
        if (kt){
            if (kt < 7) CP_WAIT1(); else CP_WAIT0();
            __syncthreads();
        }
        const uint32_t Kh_u = fs_u + 36864u + (uint32_t)((kt & 1) * 36864);
        const uint32_t Kl_u = Kh_u + 9216u;
        const uint32_t Vh_u = Kh_u + 18432u;
        const uint32_t Vl_u = Kh_u + 27648u;

        // S = Q @ K^T  (128x64 per CTA; 16x64 per warp)
        float s[8][4] = {};
        #pragma unroll
        for (int np = 0; np < 4; np++){
            #pragma unroll
            for (int kb = 0; kb < 4; kb++){
                uint32_t k4h[4], k4l[4];
                uint32_t off = koff + (uint32_t)(np * 2304) + (uint32_t)(kb << 5);
                ldsm4(k4h, Kh_u + off);
                ldsm4(k4l, Kl_u + off);
                mma16816(s[2*np],     qh[kb], k4h);
                mma16816(s[2*np],     ql[kb], k4h);
                mma16816(s[2*np],     qh[kb], k4l);
                mma16816(s[2*np+1],   qh[kb], k4h + 2);
                mma16816(s[2*np+1],   ql[kb], k4h + 2);
                mma16816(s[2*np+1],   qh[kb], k4l + 2);
            }
        }

        // mask + online softmax
        float rm0 = -INFINITY, rm1 = -INFINITY;
        #pragma unroll
        for (int nf = 0; nf < 8; nf++){
            int cg = (kt << 6) + (nf << 3) + (tg << 1);
            float ma = sM[cg], mb = sM[cg + 1];
            s[nf][0] += ma + ((cg     == qg0) ? NEGBIG : 0.f);
            s[nf][1] += mb + ((cg + 1 == qg0) ? NEGBIG : 0.f);
            s[nf][2] += ma + ((cg     == qg1) ? NEGBIG : 0.f);
            s[nf][3] += mb + ((cg + 1 == qg1) ? NEGBIG : 0.f);
            rm0 = fmaxf(rm0, fmaxf(s[nf][0], s[nf][1]));
            rm1 = fmaxf(rm1, fmaxf(s[nf][2], s[nf][3]));
        }
        rm0 = fmaxf(rm0, __shfl_xor_sync(0xffffffffu, rm0, 1));
        rm0 = fmaxf(rm0, __shfl_xor_sync(0xffffffffu, rm0, 2));
        rm1 = fmaxf(rm1, __shfl_xor_sync(0xffffffffu, rm1, 1));
        rm1 = fmaxf(rm1, __shfl_xor_sync(0xffffffffu, rm1, 2));

        float mn0 = fmaxf(mp0, rm0), mn1 = fmaxf(mp1, rm1);
        float cf0 = __expf(mp0 - mn0), cf1 = __expf(mp1 - mn1);
        float rs0 = 0.f, rs1 = 0.f;
        #pragma unroll
        for (int nf = 0; nf < 8; nf++){
            s[nf][0] = __expf(s[nf][0] - mn0);
            s[nf][1] = __expf(s[nf][1] - mn0);
            s[nf][2] = __expf(s[nf][2] - mn1);
            s[nf][3] = __expf(s[nf][3] - mn1);
            rs0 += s[nf][0] + s[nf][1];
            rs1 += s[nf][2] + s[nf][3];
        }
        rs0 += __shfl_xor_sync(0xffffffffu, rs0, 1);
        rs0 += __shfl_xor_sync(0xffffffffu, rs0, 2);
        rs1 += __shfl_xor_sync(0xffffffffu, rs1, 1);
        rs1 += __shfl_xor_sync(0xffffffffu, rs1, 2);

        l0 = l0 * cf0 + rs0;
        l1 = l1 * cf1 + rs1;
        mp0 = mn0; mp1 = mn1;
        #pragma unroll
        for (int df = 0; df < 8; df++){
            o[df][0] *= cf0; o[df][1] *= cf0;
            o[df][2] *= cf1; o[df][3] *= cf1;
        }

        // O += P @ V   (P-hi only; dropped P-lo x V-hi term, ~1e-4 final rel err)
        #pragma unroll
        for (int kb = 0; kb < 4; kb++){
            uint32_t ph[4];
            ph[0] = pack2hi(s[2*kb][0],   s[2*kb][1]);
            ph[1] = pack2hi(s[2*kb][2],   s[2*kb][3]);
            ph[2] = pack2hi(s[2*kb+1][0], s[2*kb+1][1]);
            ph[3] = pack2hi(s[2*kb+1][2], s[2*kb+1][3]);
            #pragma unroll
            for (int dp = 0; dp < 4; dp++){
                uint32_t v4h[4], v4l[4];
                uint32_t off = koff + (uint32_t)(dp * 2304) + (uint32_t)(kb << 5);
                ldsm4(v4h, Vh_u + off);
                ldsm4(v4l, Vl_u + off);
                mma16816(o[2*dp],   ph, v4h);
                mma16816(o[2*dp],   ph, v4l);
                mma16816(o[2*dp+1], ph, v4h + 2);
                mma16816(o[2*dp+1], ph, v4l + 2);
            }
        }

        __syncthreads();
        if (kt + 2 < 8) issueT(kt & 1, kt + 2);
    }

    // write ctx (bf16 split) as [b*t, e] rows for the O-projection GEMM
    float i0 = 1.f / l0, i1 = 1.f / l1;
    size_t row0 = (size_t)b * T_ + qg0;
    size_t row1 = (size_t)b * T_ + qg1;
    #pragma unroll
    for (int df = 0; df < 8; df++){
        int d = h * 64 + (df << 3) + (tg << 1);
        uint32_t hp, lp;
        pack2(o[df][0] * i0, o[df][1] * i0, hp, lp);
        *(uint32_t*)(ctxhi + row0 * E_ + d) = hp;
        *(uint32_t*)(ctxlo + row0 * E_ + d) = lp;
        pack2(o[df][2] * i1, o[df][3] * i1, hp, lp);
        *(uint32_t*)(ctxhi + row1 * E_ + d) = hp;
        *(uint32_t*)(ctxlo + row1 * E_ + d) = lp;
    }
}

// ---------------- LayerNorm + final residual ----------------
__global__ __launch_bounds__(256)
void ln_kernel(const float* __restrict__ z, const float* __restrict__ g,
               const float* __restrict__ bb, const float* __restrict__ ht,
               float* __restrict__ out)
{
    const int m = blockIdx.x;
    const int t = threadIdx.x;
    __shared__ float buf[E_];
    __shared__ float red[8];
    const int lane = t & 31, wrp = t >> 5;

    float s = 0.f;
    for (int e = t; e < E_; e += 256){
        float x = z[(size_t)m * E_ + e];
        buf[e] = x;
        s += x;
    }
    #pragma unroll
    for (int w = 16; w; w >>= 1) s += __shfl_xor_sync(0xffffffffu, s, w);
    if (lane == 0) red[wrp] = s;
    __syncthreads();
    float mu = 0.f;
    #pragma unroll
    for (int i = 0; i < 8; i++) mu += red[i];
    mu *= (1.f / E_);
    __syncthreads();

    float vs = 0.f;
    for (int e = t; e < E_; e += 256){
        float d = buf[e] - mu;
        vs += d * d;
    }
    #pragma unroll
    for (int w = 16; w; w >>= 1) vs += __shfl_xor_sync(0xffffffffu, vs, w);
    if (lane == 0) red[wrp] = vs;
    __syncthreads();
    float var = 0.f;
    #pragma unroll
    for (int i = 0; i < 8; i++) var += red[i];
    var *= (1.f / E_);
    float rs = rsqrtf(var + 1e-12f);

    for (int e = t; e < E_; e += 256){
        out[(size_t)m * E_ + e] =
            (buf[e] - mu) * rs * g[e] + bb[e] + ht[(size_t)m * E_ + e];
    }
}

// ---------------- launch ----------------
extern "C" void kernel_launch(void* const* d_in, const int* in_sizes, int n_in,
                              void* d_out, int out_size)
{
    const float* X    = (const float*)d_in[0];
    const float* amsk = (const float*)d_in[1];
    const float* TE   = (const float*)d_in[2];
    const float* tp   = (const float*)d_in[3];
    const float* Wq   = (const float*)d_in[4];
    const float* bq   = (const float*)d_in[5];
    const float* Wk   = (const float*)d_in[6];
    const float* bk   = (const float*)d_in[7];
    const float* Wv   = (const float*)d_in[8];
    const float* bv   = (const float*)d_in[9];
    const float* Wo   = (const float*)d_in[10];
    const float* bo   = (const float*)d_in[11];
    const float* lng  = (const float*)d_in[12];
    const float* lnb  = (const float*)d_in[13];

    float* out    = (float*)d_out;
    float* scores = out + (size_t)MROWS * E_;

    bf16 *pXhi, *pXlo, *patthi, *pattlo, *phthi, *phtlo, *pctxhi, *pctxlo;
    bf16 *pqhi, *pqlo, *pkhi, *pklo, *pvhi, *pvlo;
    bf16 *pWo1, *pWo2;
    bf16 *pTE1, *pTE2, *pTEt1, *pTEt2;
    float *pht, *pz, *pbq2, *pbqpart, *pscpart;
    cudaGetSymbolAddress((void**)&pXhi,   g_Xhi);
    cudaGetSymbolAddress((void**)&pXlo,   g_Xlo);
    cudaGetSymbolAddress((void**)&patthi, g_atthi);
    cudaGetSymbolAddress((void**)&pattlo, g_attlo);
    cudaGetSymbolAddress((void**)&pht,    g_ht);
    cudaGetSymbolAddress((void**)&phthi,  g_hthi);
    cudaGetSymbolAddress((void**)&phtlo,  g_htlo);
    cudaGetSymbolAddress((void**)&pqhi,   g_qhi);
    cudaGetSymbolAddress((void**)&pqlo,   g_qlo);
    cudaGetSymbolAddress((void**)&pkhi,   g_khi);
    cudaGetSymbolAddress((void**)&pklo,   g_klo);
    cudaGetSymbolAddress((void**)&pvhi,   g_vhi);
    cudaGetSymbolAddress((void**)&pvlo,   g_vlo);
    cudaGetSymbolAddress((void**)&pctxhi, g_ctxhi);
    cudaGetSymbolAddress((void**)&pctxlo, g_ctxlo);
    cudaGetSymbolAddress((void**)&pz,     g_z);
    cudaGetSymbolAddress((void**)&pWo1,   g_Wothi);
    cudaGetSymbolAddress((void**)&pWo2,   g_Wotlo);
    cudaGetSymbolAddress((void**)&pTE1,   g_TEhi);
    cudaGetSymbolAddress((void**)&pTE2,   g_TElo);
    cudaGetSymbolAddress((void**)&pTEt1,  g_TEthi);
    cudaGetSymbolAddress((void**)&pTEt2,  g_TEtlo);
    cudaGetSymbolAddress((void**)&pbq2,   g_bq2);
    cudaGetSymbolAddress((void**)&pbqpart, g_bqpart);
    cudaGetSymbolAddress((void**)&pscpart, g_scpart);

    const int gsm = 2 * (int)GSTG_BYTES;   // 81920
    cudaFuncSetAttribute(mma_gemm<2>, cudaFuncAttributeMaxDynamicSharedMemorySize, gsm);
    cudaFuncSetAttribute(mma_gemm<3>, cudaFuncAttributeMaxDynamicSharedMemorySize, gsm);
    cudaFuncSetAttribute(mma_gemm<4>, cudaFuncAttributeMaxDynamicSharedMemorySize, gsm);
    cudaFuncSetAttribute(qkv_gemm,    cudaFuncAttributeMaxDynamicSharedMemorySize, gsm);
    const int fsm_bytes = 55296 * (int)sizeof(bf16) + 512 * (int)sizeof(float); // 112640
    cudaFuncSetAttribute(flash_mma, cudaFuncAttributeMaxDynamicSharedMemorySize,
                         fsm_bytes);

    dim3 blk(256);

    // ---- prep + compute; split-K scores at launch index 3 for profiling ----
    split_kernel<<<(MROWS * E_ + 255) / 256, blk>>>(X, pXhi, pXlo, MROWS * E_);     // 0
    transW_all<<<dim3(24, 24, 4), blk>>>(Wq, Wk, Wv, Wo);                            // 1
    tePad_kernel<<<(128 * E_ + 255) / 256, blk>>>(TE, pTE1, pTE2);                   // 2
    // ---- scores halves = X @ TE^T (split-K=2) ----                                 3  (profiled)
    mma_gemm<4><<<dim3(1, 64, 2), blk, gsm>>>(pXhi, pXlo, E_, pTE1, pTE2, E_, 384,
                                              nullptr, nullptr, nullptr,
                                              pscpart, nullptr, nullptr);
    scores_reduce<<<(MROWS * L_ + 255) / 256, blk>>>(pscpart, scores);               // 4
    // ---- att = softmax(scores) ----                                                5
    softmax100_kernel<<<MROWS / 8, blk>>>(scores, patthi, pattlo);
    teT_kernel<<<(E_ * 128 + 255) / 256, blk>>>(TE, pTEt1, pTEt2);                   // 6
    biasq_part<<<dim3(3, 16), blk>>>(tp, Wq, pbqpart);                               // 7
    biasq_reduce<<<3, blk>>>(pbqpart, bq, pbq2);                                     // 8
    // ---- h_truth = att @ TE + X (fp32 + bf16 split) ----                           9
    mma_gemm<2><<<dim3(6, 64), blk, gsm>>>(patthi, pattlo, 128, pTEt1, pTEt2, 128, 128,
                                           nullptr, X, nullptr,
                                           pht, phthi, phtlo);
    // ---- q,k,v fused ----                                                         10
    qkv_gemm<<<dim3(6, 64, 3), blk, gsm>>>(bk, bv);
    // ---- flash attention ----                                                     11
    flash_mma<<<dim3(4, H_, B_), blk, fsm_bytes>>>(pqhi, pqlo, pkhi, pklo,
                                                   pvhi, pvlo, amsk,
                                                   pctxhi, pctxlo);
    // ---- z = ctx @ Wo + bo + X + tp ----                                          12
    mma_gemm<3><<<dim3(6, 64), blk, gsm>>>(pctxhi, pctxlo, E_, pWo1, pWo2, E_, E_,
                                           bo, X, tp,
                                           pz, nullptr, nullptr);
    // ---- out = LN(z) + h_truth ----                                               13
    ln_kernel<<<MROWS, blk>>>(pz, lng, lnb, pht, out);
}